// round 3
// baseline (speedup 1.0000x reference)
#include <cuda_runtime.h>
#include <cuda_bf16.h>
#include <mma.h>
#include <math.h>

using namespace nvcuda;

// ---------------- Problem constants ----------------
#define NN_NODES 17
#define HEADS 8
#define BB 128
#define TT 24
#define GPOSE 3072            // graphs per pose = B*T
#define GTOT 6144             // both poses
#define ROWS_TOT (GTOT*NN_NODES)      // 104448
#define ROWS_POSE (GPOSE*NN_NODES)    // 52224
#define FEAT 4608
#define LSTM_H 512
#define NCLS 500
#define OUT_LSTM (2*BB*2*LSTM_H)      // 256*1024 = 262144

// ---------------- Scratch (static device memory; no allocs) ----------------
__device__ float S_h[(size_t)ROWS_TOT * 2048];
__device__ float S_x[(size_t)ROWS_TOT * 1024];
__device__ float S_comb[(size_t)(2*BB) * TT * FEAT];
__device__ float S_xproj[(size_t)(2*BB) * TT * 2048];
__device__ float S_gates[(size_t)(2*BB) * 2048];
__device__ float S_gatesb[(size_t)(2*BB) * 2048];
__device__ float S_hst[(size_t)(2*BB) * LSTM_H];
__device__ float S_cst[(size_t)(2*BB) * LSTM_H];
__device__ float S_biasf[2048];
__device__ float S_biasb[2048];

// ---------------- Adjacency masks + edge list ----------------
__constant__ unsigned int ADJMASK[17] = {
    0x7u, 0xFu, 0x17u, 0x2Au, 0x54u, 0x8E8u, 0x1170u, 0x2A0u, 0x540u,
    0x280u, 0x500u, 0x3820u, 0x5840u, 0xA800u, 0x15000u, 0xA000u, 0x14000u
};
__constant__ int ESRC[38] = {15,13,16,14,11,5,6,5,5,6,7,8,1,0,0,1,2,3,4,
                             13,11,14,12,12,11,12,6,7,8,9,10,2,1,2,3,4,5,6};
__constant__ int EDST[38] = {13,11,14,12,12,11,12,6,7,8,9,10,2,1,2,3,4,5,6,
                             15,13,16,14,11,5,6,5,5,6,7,8,1,0,0,1,2,3,4};

static inline int cdiv(int a, int b) { return (a + b - 1) / b; }

// ==================================================================
// tf32 wmma GEMM: C[M,N] = A[M,K] * op(B).  BM=BN=128, BK=32, 256 thr.
// TB==0: B is [K,N] row-major.  TB==1: B is [N,K] row-major (use B^T).
// Requires: M%128==0, N%128==0, K%32==0, lda/ldb/ldc %4==0, bases 16B aligned.
// ==================================================================
template<int TB>
__global__ void __launch_bounds__(256) tf32_gemm_kernel(
    int M, int N, int K,
    const float* __restrict__ A, int lda,
    const float* __restrict__ B, int ldb,
    float* __restrict__ C, int ldc)
{
    __shared__ float As[128][36];
    __shared__ float Bs[32][132];
    const int tid  = threadIdx.x;
    const int warp = tid >> 5;
    const int wm   = warp & 3;       // 0..3 -> 32-row strip
    const int wn   = warp >> 2;      // 0..1 -> 64-col strip
    const int bm   = blockIdx.y * 128;
    const int bn   = blockIdx.x * 128;

    wmma::fragment<wmma::accumulator, 16, 16, 8, float> acc[2][4];
#pragma unroll
    for (int i = 0; i < 2; i++)
#pragma unroll
        for (int j = 0; j < 4; j++) wmma::fill_fragment(acc[i][j], 0.0f);

    for (int k0 = 0; k0 < K; k0 += 32) {
        // ---- load A tile: 128x32 floats as float4 ----
#pragma unroll
        for (int t = 0; t < 4; t++) {
            int i = tid + t * 256;          // 0..1023
            int row = i >> 3, c4 = i & 7;   // c4*4 in [0,32)
            float4 v = *reinterpret_cast<const float4*>(
                &A[(size_t)(bm + row) * lda + k0 + c4 * 4]);
            *reinterpret_cast<float4*>(&As[row][c4 * 4]) = v;
        }
        // ---- load B tile -> Bs[k][n] ----
        if (TB == 0) {
#pragma unroll
            for (int t = 0; t < 4; t++) {
                int i = tid + t * 256;
                int k = i >> 5, c4 = i & 31;
                float4 v = *reinterpret_cast<const float4*>(
                    &B[(size_t)(k0 + k) * ldb + bn + c4 * 4]);
                *reinterpret_cast<float4*>(&Bs[k][c4 * 4]) = v;
            }
        } else {
#pragma unroll
            for (int t = 0; t < 4; t++) {
                int i = tid + t * 256;
                int n = i >> 3, k4 = i & 7;
                float4 v = *reinterpret_cast<const float4*>(
                    &B[(size_t)(bn + n) * ldb + k0 + k4 * 4]);
                Bs[k4 * 4 + 0][n] = v.x;
                Bs[k4 * 4 + 1][n] = v.y;
                Bs[k4 * 4 + 2][n] = v.z;
                Bs[k4 * 4 + 3][n] = v.w;
            }
        }
        __syncthreads();

#pragma unroll
        for (int kk = 0; kk < 32; kk += 8) {
            wmma::fragment<wmma::matrix_a, 16, 16, 8, wmma::precision::tf32, wmma::row_major> af[2];
            wmma::fragment<wmma::matrix_b, 16, 16, 8, wmma::precision::tf32, wmma::row_major> bf[4];
#pragma unroll
            for (int i = 0; i < 2; i++) {
                wmma::load_matrix_sync(af[i], &As[wm * 32 + i * 16][kk], 36);
#pragma unroll
                for (int e = 0; e < af[i].num_elements; e++)
                    af[i].x[e] = wmma::__float_to_tf32(af[i].x[e]);
            }
#pragma unroll
            for (int j = 0; j < 4; j++) {
                wmma::load_matrix_sync(bf[j], &Bs[kk][wn * 64 + j * 16], 132);
#pragma unroll
                for (int e = 0; e < bf[j].num_elements; e++)
                    bf[j].x[e] = wmma::__float_to_tf32(bf[j].x[e]);
            }
#pragma unroll
            for (int i = 0; i < 2; i++)
#pragma unroll
                for (int j = 0; j < 4; j++)
                    wmma::mma_sync(acc[i][j], af[i], bf[j], acc[i][j]);
        }
        __syncthreads();
    }

#pragma unroll
    for (int i = 0; i < 2; i++)
#pragma unroll
        for (int j = 0; j < 4; j++)
            wmma::store_matrix_sync(
                &C[(size_t)(bm + wm * 32 + i * 16) * ldc + bn + wn * 64 + j * 16],
                acc[i][j], ldc, wmma::mem_row_major);
}

// ---------------- Generic fp32 register-blocked GEMM (small/odd shapes) ----------------
template<int BM, int BN, int BK, int TM, int TN, int TB>
__global__ void sgemm_kernel(int M, int N, int K,
                             const float* __restrict__ A, int lda,
                             const float* __restrict__ B, int ldb,
                             float* __restrict__ C, int ldc,
                             const float* __restrict__ bias,
                             const float* __restrict__ addmat, int ldadd)
{
    constexpr int THREADS = (BM/TM) * (BN/TN);
    __shared__ float As[BK][BM];
    __shared__ float Bs[BK][BN];
    const int tid = threadIdx.x;
    const int bm = blockIdx.y * BM;
    const int bn = blockIdx.x * BN;
    const int tx = tid % (BN/TN);
    const int ty = tid / (BN/TN);

    float acc[TM][TN];
#pragma unroll
    for (int i = 0; i < TM; i++)
#pragma unroll
        for (int j = 0; j < TN; j++) acc[i][j] = 0.f;

    for (int k0 = 0; k0 < K; k0 += BK) {
        for (int i = tid; i < BM*BK; i += THREADS) {
            int m = i / BK, k = i % BK;
            int gm = bm + m, gk = k0 + k;
            As[k][m] = (gm < M && gk < K) ? A[(size_t)gm * lda + gk] : 0.f;
        }
        if (TB == 0) {
            for (int i = tid; i < BK*BN; i += THREADS) {
                int k = i / BN, n = i % BN;
                int gk = k0 + k, gn = bn + n;
                Bs[k][n] = (gk < K && gn < N) ? B[(size_t)gk * ldb + gn] : 0.f;
            }
        } else {
            for (int i = tid; i < BK*BN; i += THREADS) {
                int n = i / BK, k = i % BK;
                int gk = k0 + k, gn = bn + n;
                Bs[k][n] = (gk < K && gn < N) ? B[(size_t)gn * ldb + gk] : 0.f;
            }
        }
        __syncthreads();
#pragma unroll
        for (int k = 0; k < BK; k++) {
            float ra[TM], rb[TN];
#pragma unroll
            for (int i = 0; i < TM; i++) ra[i] = As[k][ty*TM + i];
#pragma unroll
            for (int j = 0; j < TN; j++) rb[j] = Bs[k][tx*TN + j];
#pragma unroll
            for (int i = 0; i < TM; i++)
#pragma unroll
                for (int j = 0; j < TN; j++) acc[i][j] += ra[i] * rb[j];
        }
        __syncthreads();
    }

#pragma unroll
    for (int i = 0; i < TM; i++) {
        int gm = bm + ty*TM + i;
        if (gm >= M) continue;
#pragma unroll
        for (int j = 0; j < TN; j++) {
            int gn = bn + tx*TN + j;
            if (gn >= N) continue;
            float v = acc[i][j];
            if (bias)   v += bias[gn];
            if (addmat) v += addmat[(size_t)gm * ldadd + gn];
            C[(size_t)gm * ldc + gn] = v;
        }
    }
}

// ---------------- GAT attention (concat layers 1&2) ----------------
template<int D>
__global__ void gat_attn_concat(const float* __restrict__ h,
                                const float* __restrict__ a_src,
                                const float* __restrict__ a_dst,
                                const float* __restrict__ bias,
                                float* __restrict__ out, int ld)
{
    __shared__ float hb[17*D];
    __shared__ float ss[17], sd[17];
    __shared__ float alpha[17*17];
    const int g = blockIdx.x >> 3;
    const int head = blockIdx.x & 7;
    const int tid = threadIdx.x;

    for (int idx = tid; idx < 17*D; idx += blockDim.x) {
        int n = idx / D, d = idx % D;
        hb[idx] = h[(size_t)(g*17 + n) * ld + head*D + d];
    }
    __syncthreads();
    if (tid < 34) {
        int n = tid % 17;
        const float* a = (tid < 17 ? a_src : a_dst) + head*D;
        float s = 0.f;
        for (int d = 0; d < D; d++) s += hb[n*D + d] * a[d];
        if (tid < 17) ss[n] = s; else sd[n] = s;
    }
    __syncthreads();
    if (tid < 17) {
        int i = tid;
        unsigned m = ADJMASK[i];
        float ev[17];
        float mx = -1e30f;
#pragma unroll
        for (int j = 0; j < 17; j++) {
            if ((m >> j) & 1u) {
                float e = sd[i] + ss[j];
                e = e > 0.f ? e : 0.2f * e;
                ev[j] = e;
                if (e > mx) mx = e;
            }
        }
        float sum = 0.f;
#pragma unroll
        for (int j = 0; j < 17; j++) {
            float a_ = 0.f;
            if ((m >> j) & 1u) { a_ = expf(ev[j] - mx); sum += a_; }
            alpha[i*17 + j] = a_;
        }
        float inv = 1.f / sum;
#pragma unroll
        for (int j = 0; j < 17; j++) alpha[i*17 + j] *= inv;
    }
    __syncthreads();
    for (int idx = tid; idx < 17*D; idx += blockDim.x) {
        int i = idx / D, d = idx % D;
        float accv = 0.f;
#pragma unroll
        for (int j = 0; j < 17; j++) accv += alpha[i*17 + j] * hb[j*D + d];
        float v = accv + bias[head*D + d];
        v = v > 0.f ? v : expm1f(v);           // ELU
        out[(size_t)(g*17 + i) * ld + head*D + d] = v;
    }
}

// ---------------- GAT layer 3 attention (mean over heads) + BN fold -> comb ----------------
__global__ void gat_attn_mean(const float* __restrict__ h,
                              const float* __restrict__ a_src,
                              const float* __restrict__ a_dst,
                              const float* __restrict__ b3,
                              float* __restrict__ comb,
                              const float* __restrict__ bn_g,
                              const float* __restrict__ bn_b,
                              const float* __restrict__ bn_mean,
                              const float* __restrict__ bn_var)
{
    const int D = 256;
    __shared__ float hb[17*256];
    __shared__ float accs[17*256];
    __shared__ float ss[17], sd[17];
    __shared__ float alpha[17*17];
    const int g = blockIdx.x;
    const int tid = threadIdx.x;

    for (int idx = tid; idx < 17*D; idx += blockDim.x) accs[idx] = 0.f;

    for (int head = 0; head < 8; head++) {
        __syncthreads();
        for (int idx = tid; idx < 17*D; idx += blockDim.x) {
            int n = idx / D, d = idx % D;
            hb[idx] = h[(size_t)(g*17 + n) * 2048 + head*D + d];
        }
        __syncthreads();
        if (tid < 34) {
            int n = tid % 17;
            const float* a = (tid < 17 ? a_src : a_dst) + head*D;
            float s = 0.f;
            for (int d = 0; d < D; d++) s += hb[n*D + d] * a[d];
            if (tid < 17) ss[n] = s; else sd[n] = s;
        }
        __syncthreads();
        if (tid < 17) {
            int i = tid;
            unsigned m = ADJMASK[i];
            float ev[17];
            float mx = -1e30f;
#pragma unroll
            for (int j = 0; j < 17; j++) {
                if ((m >> j) & 1u) {
                    float e = sd[i] + ss[j];
                    e = e > 0.f ? e : 0.2f * e;
                    ev[j] = e;
                    if (e > mx) mx = e;
                }
            }
            float sum = 0.f;
#pragma unroll
            for (int j = 0; j < 17; j++) {
                float a_ = 0.f;
                if ((m >> j) & 1u) { a_ = expf(ev[j] - mx); sum += a_; }
                alpha[i*17 + j] = a_;
            }
            float inv = 1.f / sum;
#pragma unroll
            for (int j = 0; j < 17; j++) alpha[i*17 + j] *= inv;
        }
        __syncthreads();
        for (int idx = tid; idx < 17*D; idx += blockDim.x) {
            int i = idx / D, d = idx % D;
            float a_ = 0.f;
#pragma unroll
            for (int j = 0; j < 17; j++) a_ += alpha[i*17 + j] * hb[j*D + d];
            accs[idx] += a_;
        }
    }
    __syncthreads();
    int p = g / GPOSE, r = g % GPOSE, b = r / TT, t = r % TT;
    float scale = bn_g[t] * rsqrtf(bn_var[t] + 1e-5f);
    float mu = bn_mean[t], beta = bn_b[t];
    size_t base = ((size_t)(p*BB + b) * TT + t) * FEAT;
    for (int idx = tid; idx < 17*D; idx += blockDim.x) {
        int n = idx / D, d = idx % D;
        float v = accs[idx] * 0.125f + b3[d];
        comb[base + n*D + d] = (v - mu) * scale + beta;
    }
}

// ---------------- Edge features + FC + BN fold (comb[..., 4352:4608]) ----------------
__global__ void edge_fc_kernel(const float* __restrict__ pose1,
                               const float* __restrict__ pose2,
                               const float* __restrict__ fc_w,
                               const float* __restrict__ fc_b,
                               float* __restrict__ comb,
                               const float* __restrict__ bn_g,
                               const float* __restrict__ bn_b,
                               const float* __restrict__ bn_mean,
                               const float* __restrict__ bn_var)
{
    __shared__ float feat[76];
    const int g = blockIdx.x;
    const int tid = threadIdx.x;
    int p = g / GPOSE, r = g % GPOSE, b = r / TT, t = r % TT;
    const float* pose = (p == 0 ? pose1 : pose2) + (size_t)r * 17 * 3;
    if (tid < 38) {
        int s = ESRC[tid], d = EDST[tid];
        float vx = pose[d*3 + 0] - pose[s*3 + 0];
        float vy = pose[d*3 + 1] - pose[s*3 + 1];
        feat[2*tid]     = sqrtf(vx*vx + vy*vy);
        feat[2*tid + 1] = atan2f(vy, vx);
    }
    __syncthreads();
    float scale = bn_g[t] * rsqrtf(bn_var[t] + 1e-5f);
    float mu = bn_mean[t], beta = bn_b[t];
    size_t base = ((size_t)(p*BB + b) * TT + t) * FEAT + 17*256;
    if (tid < 128) {
        float s0 = fc_b[tid], s1 = fc_b[tid];
        for (int j = 0; j < 38; j++) {
            float w = fc_w[j*128 + tid];
            s0 += feat[j] * w;
            s1 += feat[38 + j] * w;
        }
        comb[base + tid]       = (s0 - mu) * scale + beta;
        comb[base + 128 + tid] = (s1 - mu) * scale + beta;
    }
}

// ---------------- Misc small kernels ----------------
__global__ void bias_sum_kernel(const float* bihf, const float* bhhf,
                                const float* bihb, const float* bhhb)
{
    int i = blockIdx.x * blockDim.x + threadIdx.x;
    if (i < 2048) {
        S_biasf[i] = bihf[i] + bhhf[i];
        S_biasb[i] = bihb[i] + bhhb[i];
    }
}

__global__ void zero_state_kernel()
{
    int i = blockIdx.x * blockDim.x + threadIdx.x;
    if (i < 2*BB*LSTM_H) { S_hst[i] = 0.f; S_cst[i] = 0.f; }
}

__device__ __forceinline__ float sigf(float x) { return 1.f / (1.f + expf(-x)); }

__global__ void lstm_cell_kernel(const float* __restrict__ gates, int gstride,
                                 const float* __restrict__ bias,
                                 float* __restrict__ h, float* __restrict__ c,
                                 float* __restrict__ out_last, int write_last)
{
    int idx = blockIdx.x * blockDim.x + threadIdx.x;
    if (idx >= 2*BB*LSTM_H) return;
    int m = idx / LSTM_H, j = idx % LSTM_H;
    const float* gm = gates + (size_t)m * gstride;
    float gi = gm[j]        + bias[j];
    float gf = gm[512 + j]  + bias[512 + j];
    float gg = gm[1024 + j] + bias[1024 + j];
    float go = gm[1536 + j] + bias[1536 + j];
    float cn = sigf(gf) * c[idx] + sigf(gi) * tanhf(gg);
    float hn = sigf(go) * tanhf(cn);
    c[idx] = cn;
    h[idx] = hn;
    if (write_last) out_last[(size_t)m * (2*LSTM_H) + j] = hn;
}

__global__ void lstm_bcell_kernel(const float* __restrict__ gates,
                                  const float* __restrict__ bias,
                                  float* __restrict__ out)
{
    int idx = blockIdx.x * blockDim.x + threadIdx.x;
    if (idx >= 2*BB*LSTM_H) return;
    int m = idx / LSTM_H, j = idx % LSTM_H;
    const float* gm = gates + (size_t)m * 2048;
    float gi = gm[j]        + bias[j];
    float gg = gm[1024 + j] + bias[1024 + j];
    float go = gm[1536 + j] + bias[1536 + j];
    float cn = sigf(gi) * tanhf(gg);
    out[(size_t)m * (2*LSTM_H) + LSTM_H + j] = sigf(go) * tanhf(cn);
}

// ---------------- Host driver ----------------
extern "C" void kernel_launch(void* const* d_in, const int* in_sizes, int n_in,
                              void* d_out, int out_size)
{
    const float* pose1 = (const float*)d_in[0];
    const float* pose2 = (const float*)d_in[1];
    const float* W1  = (const float*)d_in[3];
    const float* as1 = (const float*)d_in[4];
    const float* ad1 = (const float*)d_in[5];
    const float* b1  = (const float*)d_in[6];
    const float* W2  = (const float*)d_in[7];
    const float* as2 = (const float*)d_in[8];
    const float* ad2 = (const float*)d_in[9];
    const float* b2  = (const float*)d_in[10];
    const float* W3  = (const float*)d_in[11];
    const float* as3 = (const float*)d_in[12];
    const float* ad3 = (const float*)d_in[13];
    const float* b3  = (const float*)d_in[14];
    const float* fc_w = (const float*)d_in[15];
    const float* fc_b = (const float*)d_in[16];
    const float* bn_g = (const float*)d_in[17];
    const float* bn_b = (const float*)d_in[18];
    const float* bn_mean = (const float*)d_in[19];
    const float* bn_var  = (const float*)d_in[20];
    const float* Wih_f = (const float*)d_in[21];
    const float* Whh_f = (const float*)d_in[22];
    const float* bih_f = (const float*)d_in[23];
    const float* bhh_f = (const float*)d_in[24];
    const float* Wih_b = (const float*)d_in[25];
    const float* Whh_b = (const float*)d_in[26];
    const float* bih_b = (const float*)d_in[27];
    const float* bhh_b = (const float*)d_in[28];
    const float* cls_w = (const float*)d_in[29];
    const float* cls_b = (const float*)d_in[30];

    float* out = (float*)d_out;

    float *g_h, *g_x, *g_comb, *g_xproj, *g_gates, *g_gatesb, *g_hst, *g_cst, *g_biasf, *g_biasb;
    cudaGetSymbolAddress((void**)&g_h, S_h);
    cudaGetSymbolAddress((void**)&g_x, S_x);
    cudaGetSymbolAddress((void**)&g_comb, S_comb);
    cudaGetSymbolAddress((void**)&g_xproj, S_xproj);
    cudaGetSymbolAddress((void**)&g_gates, S_gates);
    cudaGetSymbolAddress((void**)&g_gatesb, S_gatesb);
    cudaGetSymbolAddress((void**)&g_hst, S_hst);
    cudaGetSymbolAddress((void**)&g_cst, S_cst);
    cudaGetSymbolAddress((void**)&g_biasf, S_biasf);
    cudaGetSymbolAddress((void**)&g_biasb, S_biasb);

    // ---- GAT layer 1: h1 = pose @ W1 (K=3) — fp32, memory-bound ----
    {
        dim3 grid(cdiv(512, 128), cdiv(ROWS_POSE, 128));
        sgemm_kernel<128,128,8,8,8,0><<<grid, 256>>>(
            ROWS_POSE, 512, 3, pose1, 3, W1, 512, g_h, 512, nullptr, nullptr, 0);
        sgemm_kernel<128,128,8,8,8,0><<<grid, 256>>>(
            ROWS_POSE, 512, 3, pose2, 3, W1, 512, g_h + (size_t)ROWS_POSE*512, 512,
            nullptr, nullptr, 0);
    }
    gat_attn_concat<64><<<GTOT*HEADS, 128>>>(g_h, as1, ad1, b1, g_x, 512);

    // ---- GAT layer 2: tf32 tensor cores (104448 x 1024 x 512) ----
    tf32_gemm_kernel<0><<<dim3(1024/128, ROWS_TOT/128), 256>>>(
        ROWS_TOT, 1024, 512, g_x, 512, W2, 1024, g_h, 1024);
    gat_attn_concat<128><<<GTOT*HEADS, 128>>>(g_h, as2, ad2, b2, g_x, 1024);

    // ---- GAT layer 3: tf32 (104448 x 2048 x 1024) ----
    tf32_gemm_kernel<0><<<dim3(2048/128, ROWS_TOT/128), 256>>>(
        ROWS_TOT, 2048, 1024, g_x, 1024, W3, 2048, g_h, 2048);
    gat_attn_mean<<<GTOT, 256>>>(g_h, as3, ad3, b3, g_comb,
                                 bn_g, bn_b, bn_mean, bn_var);

    // ---- edge features + FC (BN folded) ----
    edge_fc_kernel<<<GTOT, 128>>>(pose1, pose2, fc_w, fc_b, g_comb,
                                  bn_g, bn_b, bn_mean, bn_var);

    // ---- gate biases ----
    bias_sum_kernel<<<8, 256>>>(bih_f, bhh_f, bih_b, bhh_b);

    // ---- forward input projection: tf32 (6144 x 2048 x 4608), B=Wih_f^T ----
    tf32_gemm_kernel<1><<<dim3(2048/128, (2*BB*TT)/128), 256>>>(
        2*BB*TT, 2048, FEAT, g_comb, FEAT, Wih_f, FEAT, g_xproj, 2048);

    // ---- backward: single step at t=23: tf32 (256 x 2048 x 4608) ----
    tf32_gemm_kernel<1><<<dim3(2048/128, (2*BB)/128), 256>>>(
        2*BB, 2048, FEAT, g_comb + (size_t)23*FEAT, TT*FEAT, Wih_b, FEAT,
        g_gatesb, 2048);
    lstm_bcell_kernel<<<cdiv(2*BB*LSTM_H, 256), 256>>>(g_gatesb, g_biasb, out);

    // ---- forward recurrence: 24 steps (fp32 for accuracy) ----
    zero_state_kernel<<<cdiv(2*BB*LSTM_H, 256), 256>>>();
    // t = 0: h=0 -> gates are just xproj slice
    lstm_cell_kernel<<<cdiv(2*BB*LSTM_H, 256), 256>>>(
        g_xproj, TT*2048, g_biasf, g_hst, g_cst, out, 0);
    for (int t = 1; t < TT; t++) {
        dim3 grid(cdiv(2048, 64), cdiv(2*BB, 64));
        sgemm_kernel<64,64,8,4,4,1><<<grid, 256>>>(
            2*BB, 2048, LSTM_H, g_hst, LSTM_H, Whh_f, LSTM_H,
            g_gates, 2048, nullptr, g_xproj + (size_t)t*2048, TT*2048);
        lstm_cell_kernel<<<cdiv(2*BB*LSTM_H, 256), 256>>>(
            g_gates, 2048, g_biasf, g_hst, g_cst, out, (t == TT-1) ? 1 : 0);
    }

    // ---- classifier: logits = lstm_out @ cls_w + cls_b (fp32) ----
    {
        dim3 grid(cdiv(NCLS, 64), cdiv(2*BB, 64));
        sgemm_kernel<64,64,8,4,4,0><<<grid, 256>>>(
            2*BB, NCLS, 2*LSTM_H, out, 2*LSTM_H, cls_w, NCLS,
            out + OUT_LSTM, NCLS, cls_b, nullptr, 0);
    }
}

// round 10
// speedup vs baseline: 2.4181x; 2.4181x over previous
#include <cuda_runtime.h>
#include <cuda_fp16.h>
#include <mma.h>
#include <math.h>
#include <stdint.h>

using namespace nvcuda;

// ---------------- Problem constants ----------------
#define NN_NODES 17
#define HEADS 8
#define BB 128
#define TT 24
#define GPOSE 3072
#define GTOT 6144
#define ROWS_TOT (GTOT*NN_NODES)      // 104448 = 816*128
#define ROWS_POSE (GPOSE*NN_NODES)    // 52224
#define FEAT 4608
#define LSTM_H 512
#define NCLS 500
#define OUT_LSTM (2*BB*2*LSTM_H)

// ---------------- Scratch (static device memory; no allocs) ----------------
__device__ float  S_h[(size_t)ROWS_TOT * 2048];         // fp32 GEMM outputs
__device__ __half S_xh[(size_t)ROWS_TOT * 1024];        // half activations (GEMM A)
__device__ __half S_combh[(size_t)(2*BB) * TT * FEAT];  // half comb (GEMM A)
__device__ float  S_xproj[(size_t)(2*BB) * TT * 2048];
__device__ float  S_gates[(size_t)(2*BB) * 2048];
__device__ float  S_gatesb[(size_t)(2*BB) * 2048];
__device__ float  S_hst[(size_t)(2*BB) * LSTM_H];
__device__ float  S_cst[(size_t)(2*BB) * LSTM_H];
__device__ float  S_biasf[2048];
__device__ float  S_biasb[2048];
__device__ __half S_w2t[(size_t)1024 * 512];    // W2^T  [1024,512] half
__device__ __half S_w3t[(size_t)2048 * 1024];   // W3^T  [2048,1024] half
__device__ __half S_wihf[(size_t)2048 * FEAT];  // Wih_f half ([2048,4608])
__device__ __half S_wihb[(size_t)2048 * FEAT];  // Wih_b half

__constant__ unsigned int ADJMASK[17] = {
    0x7u, 0xFu, 0x17u, 0x2Au, 0x54u, 0x8E8u, 0x1170u, 0x2A0u, 0x540u,
    0x280u, 0x500u, 0x3820u, 0x5840u, 0xA800u, 0x15000u, 0xA000u, 0x14000u
};
__constant__ int ESRC[38] = {15,13,16,14,11,5,6,5,5,6,7,8,1,0,0,1,2,3,4,
                             13,11,14,12,12,11,12,6,7,8,9,10,2,1,2,3,4,5,6};
__constant__ int EDST[38] = {13,11,14,12,12,11,12,6,7,8,9,10,2,1,2,3,4,5,6,
                             15,13,16,14,11,5,6,5,5,6,7,8,1,0,0,1,2,3,4};

static inline int cdiv(int a, int b) { return (a + b - 1) / b; }

// =======================================================================
// fp16 wmma GEMM (TN): C[M,N](f32) = A[M,K](half,row) * B[N,K](half,row)^T
// BM=BN=128, BK=32, 256 threads, 2-stage cp.async double buffering.
// Requires M%128==0, N%128==0, K%32==0, lda/ldb %8==0.
// =======================================================================
__device__ __forceinline__ uint32_t smem_u32h(const void* p) {
    return (uint32_t)__cvta_generic_to_shared(p);
}
__device__ __forceinline__ void cpasync16h(uint32_t dst, const void* src) {
    asm volatile("cp.async.cg.shared.global [%0], [%1], 16;" :: "r"(dst), "l"(src));
}

__global__ void __launch_bounds__(256, 2) hgemm_tn(
    int M, int N, int K,
    const __half* __restrict__ A, int lda,
    const __half* __restrict__ B, int ldb,
    float* __restrict__ C, int ldc)
{
    __shared__ __half As[2][128][40];
    __shared__ __half Bs[2][128][40];
    const int tid  = threadIdx.x;
    const int warp = tid >> 5;
    const int wm   = warp & 3;      // 32-row strip
    const int wn   = warp >> 2;     // 64-col strip
    const int bm   = blockIdx.y * 128;
    const int bn   = blockIdx.x * 128;
    const int T    = K >> 5;

    wmma::fragment<wmma::accumulator, 16, 16, 16, float> acc[2][4];
#pragma unroll
    for (int i = 0; i < 2; i++)
#pragma unroll
        for (int j = 0; j < 4; j++) wmma::fill_fragment(acc[i][j], 0.0f);

    const uint32_t as_base = smem_u32h(&As[0][0][0]);
    const uint32_t bs_base = smem_u32h(&Bs[0][0][0]);
    const uint32_t stage_bytes = 128 * 40 * 2;   // 10240

    auto load_stage = [&](int s, int kt) {
        const __half* a = A + (size_t)bm * lda + kt * 32;
        const __half* b = B + (size_t)bn * ldb + kt * 32;
#pragma unroll
        for (int i = 0; i < 2; i++) {
            int q = tid + i * 256;           // 0..511
            int row = q >> 2, c = q & 3;     // c*8 halves = 16B
            cpasync16h(as_base + s * stage_bytes + row * 80 + c * 16,
                       a + (size_t)row * lda + c * 8);
        }
#pragma unroll
        for (int i = 0; i < 2; i++) {
            int q = tid + i * 256;
            int row = q >> 2, c = q & 3;
            cpasync16h(bs_base + s * stage_bytes + row * 80 + c * 16,
                       b + (size_t)row * ldb + c * 8);
        }
    };

    load_stage(0, 0);
    asm volatile("cp.async.commit_group;" ::: "memory");

    for (int kt = 0; kt < T; kt++) {
        const int s = kt & 1;
        if (kt + 1 < T) {
            load_stage(s ^ 1, kt + 1);
            asm volatile("cp.async.commit_group;" ::: "memory");
            asm volatile("cp.async.wait_group 1;" ::: "memory");
        } else {
            asm volatile("cp.async.wait_group 0;" ::: "memory");
        }
        __syncthreads();

#pragma unroll
        for (int kk = 0; kk < 32; kk += 16) {
            wmma::fragment<wmma::matrix_a, 16, 16, 16, __half, wmma::row_major> af[2];
            wmma::load_matrix_sync(af[0], &As[s][wm * 32][kk], 40);
            wmma::load_matrix_sync(af[1], &As[s][wm * 32 + 16][kk], 40);
#pragma unroll
            for (int j = 0; j < 4; j++) {
                wmma::fragment<wmma::matrix_b, 16, 16, 16, __half, wmma::col_major> bf;
                wmma::load_matrix_sync(bf, &Bs[s][wn * 64 + j * 16][kk], 40);
                wmma::mma_sync(acc[0][j], af[0], bf, acc[0][j]);
                wmma::mma_sync(acc[1][j], af[1], bf, acc[1][j]);
            }
        }
        __syncthreads();
    }

#pragma unroll
    for (int i = 0; i < 2; i++)
#pragma unroll
        for (int j = 0; j < 4; j++)
            wmma::store_matrix_sync(
                &C[(size_t)(bm + wm * 32 + i * 16) * ldc + bn + wn * 64 + j * 16],
                acc[i][j], ldc, wmma::mem_row_major);
}

// ---------------- weight conversion kernels ----------------
__global__ void f2h_kernel(const float* __restrict__ in, __half* __restrict__ out, size_t n)
{
    for (size_t i = (size_t)blockIdx.x * blockDim.x + threadIdx.x; i < n;
         i += (size_t)gridDim.x * blockDim.x)
        out[i] = __float2half(in[i]);
}

// out[c][r] = (half) in[r][c]   (in: [R,C] fp32 -> out: [C,R] half)
__global__ void transpose_h_kernel(const float* __restrict__ in, __half* __restrict__ out,
                                   int R, int Ccols)
{
    __shared__ float t[32][33];
    int bx = blockIdx.x * 32, by = blockIdx.y * 32;
#pragma unroll
    for (int dy = 0; dy < 32; dy += 8) {
        int r = by + threadIdx.y + dy, c = bx + threadIdx.x;
        if (r < R && c < Ccols) t[threadIdx.y + dy][threadIdx.x] = in[(size_t)r * Ccols + c];
    }
    __syncthreads();
#pragma unroll
    for (int dy = 0; dy < 32; dy += 8) {
        int r = bx + threadIdx.y + dy, c = by + threadIdx.x;
        if (r < Ccols && c < R) out[(size_t)r * R + c] = __float2half(t[threadIdx.x][threadIdx.y + dy]);
    }
}

// ---------------- fp32 GEMM (small/odd shapes) ----------------
template<int BM, int BN, int BK, int TM, int TN, int TB>
__global__ void sgemm_kernel(int M, int N, int K,
                             const float* __restrict__ A, int lda,
                             const float* __restrict__ B, int ldb,
                             float* __restrict__ C, int ldc,
                             const float* __restrict__ bias,
                             const float* __restrict__ addmat, int ldadd)
{
    constexpr int THREADS = (BM/TM) * (BN/TN);
    __shared__ float As[BK][BM];
    __shared__ float Bs[BK][BN];
    const int tid = threadIdx.x;
    const int bm = blockIdx.y * BM;
    const int bn = blockIdx.x * BN;
    const int tx = tid % (BN/TN);
    const int ty = tid / (BN/TN);

    float acc[TM][TN];
#pragma unroll
    for (int i = 0; i < TM; i++)
#pragma unroll
        for (int j = 0; j < TN; j++) acc[i][j] = 0.f;

    for (int k0 = 0; k0 < K; k0 += BK) {
        for (int i = tid; i < BM*BK; i += THREADS) {
            int m = i / BK, k = i % BK;
            int gm = bm + m, gk = k0 + k;
            As[k][m] = (gm < M && gk < K) ? A[(size_t)gm * lda + gk] : 0.f;
        }
        if (TB == 0) {
            for (int i = tid; i < BK*BN; i += THREADS) {
                int k = i / BN, n = i % BN;
                int gk = k0 + k, gn = bn + n;
                Bs[k][n] = (gk < K && gn < N) ? B[(size_t)gk * ldb + gn] : 0.f;
            }
        } else {
            for (int i = tid; i < BK*BN; i += THREADS) {
                int n = i / BK, k = i % BK;
                int gk = k0 + k, gn = bn + n;
                Bs[k][n] = (gk < K && gn < N) ? B[(size_t)gn * ldb + gk] : 0.f;
            }
        }
        __syncthreads();
#pragma unroll
        for (int k = 0; k < BK; k++) {
            float ra[TM], rb[TN];
#pragma unroll
            for (int i = 0; i < TM; i++) ra[i] = As[k][ty*TM + i];
#pragma unroll
            for (int j = 0; j < TN; j++) rb[j] = Bs[k][tx*TN + j];
#pragma unroll
            for (int i = 0; i < TM; i++)
#pragma unroll
                for (int j = 0; j < TN; j++) acc[i][j] += ra[i] * rb[j];
        }
        __syncthreads();
    }

#pragma unroll
    for (int i = 0; i < TM; i++) {
        int gm = bm + ty*TM + i;
        if (gm >= M) continue;
#pragma unroll
        for (int j = 0; j < TN; j++) {
            int gn = bn + tx*TN + j;
            if (gn >= N) continue;
            float v = acc[i][j];
            if (bias)   v += bias[gn];
            if (addmat) v += addmat[(size_t)gm * ldadd + gn];
            C[(size_t)gm * ldc + gn] = v;
        }
    }
}

// ---------------- GAT attention (concat layers 1&2) -> half output ----------------
template<int D>
__global__ void gat_attn_concat(const float* __restrict__ h,
                                const float* __restrict__ a_src,
                                const float* __restrict__ a_dst,
                                const float* __restrict__ bias,
                                __half* __restrict__ out, int ld)
{
    __shared__ float hb[17*D];
    __shared__ float ss[17], sd[17];
    __shared__ float alpha[17*17];
    const int g = blockIdx.x >> 3;
    const int head = blockIdx.x & 7;
    const int tid = threadIdx.x;

    for (int idx = tid; idx < 17*D; idx += blockDim.x) {
        int n = idx / D, d = idx % D;
        hb[idx] = h[(size_t)(g*17 + n) * ld + head*D + d];
    }
    __syncthreads();
    if (tid < 34) {
        int n = tid % 17;
        const float* a = (tid < 17 ? a_src : a_dst) + head*D;
        float s = 0.f;
        for (int d = 0; d < D; d++) s += hb[n*D + d] * a[d];
        if (tid < 17) ss[n] = s; else sd[n] = s;
    }
    __syncthreads();
    if (tid < 17) {
        int i = tid;
        unsigned m = ADJMASK[i];
        float ev[17];
        float mx = -1e30f;
#pragma unroll
        for (int j = 0; j < 17; j++) {
            if ((m >> j) & 1u) {
                float e = sd[i] + ss[j];
                e = e > 0.f ? e : 0.2f * e;
                ev[j] = e;
                if (e > mx) mx = e;
            }
        }
        float sum = 0.f;
#pragma unroll
        for (int j = 0; j < 17; j++) {
            float a_ = 0.f;
            if ((m >> j) & 1u) { a_ = expf(ev[j] - mx); sum += a_; }
            alpha[i*17 + j] = a_;
        }
        float inv = 1.f / sum;
#pragma unroll
        for (int j = 0; j < 17; j++) alpha[i*17 + j] *= inv;
    }
    __syncthreads();
    for (int idx = tid; idx < 17*D; idx += blockDim.x) {
        int i = idx / D, d = idx % D;
        float accv = 0.f;
#pragma unroll
        for (int j = 0; j < 17; j++) accv += alpha[i*17 + j] * hb[j*D + d];
        float v = accv + bias[head*D + d];
        v = v > 0.f ? v : expm1f(v);           // ELU
        out[(size_t)(g*17 + i) * ld + head*D + d] = __float2half(v);
    }
}

// ---------------- GAT layer 3 (mean heads) + BN fold -> half comb ----------------
__global__ void gat_attn_mean(const float* __restrict__ h,
                              const float* __restrict__ a_src,
                              const float* __restrict__ a_dst,
                              const float* __restrict__ b3,
                              __half* __restrict__ comb,
                              const float* __restrict__ bn_g,
                              const float* __restrict__ bn_b,
                              const float* __restrict__ bn_mean,
                              const float* __restrict__ bn_var)
{
    const int D = 256;
    __shared__ float hb[17*256];
    __shared__ float accs[17*256];
    __shared__ float ss[17], sd[17];
    __shared__ float alpha[17*17];
    const int g = blockIdx.x;
    const int tid = threadIdx.x;

    for (int idx = tid; idx < 17*D; idx += blockDim.x) accs[idx] = 0.f;

    for (int head = 0; head < 8; head++) {
        __syncthreads();
        for (int idx = tid; idx < 17*D; idx += blockDim.x) {
            int n = idx / D, d = idx % D;
            hb[idx] = h[(size_t)(g*17 + n) * 2048 + head*D + d];
        }
        __syncthreads();
        if (tid < 34) {
            int n = tid % 17;
            const float* a = (tid < 17 ? a_src : a_dst) + head*D;
            float s = 0.f;
            for (int d = 0; d < D; d++) s += hb[n*D + d] * a[d];
            if (tid < 17) ss[n] = s; else sd[n] = s;
        }
        __syncthreads();
        if (tid < 17) {
            int i = tid;
            unsigned m = ADJMASK[i];
            float ev[17];
            float mx = -1e30f;
#pragma unroll
            for (int j = 0; j < 17; j++) {
                if ((m >> j) & 1u) {
                    float e = sd[i] + ss[j];
                    e = e > 0.f ? e : 0.2f * e;
                    ev[j] = e;
                    if (e > mx) mx = e;
                }
            }
            float sum = 0.f;
#pragma unroll
            for (int j = 0; j < 17; j++) {
                float a_ = 0.f;
                if ((m >> j) & 1u) { a_ = expf(ev[j] - mx); sum += a_; }
                alpha[i*17 + j] = a_;
            }
            float inv = 1.f / sum;
#pragma unroll
            for (int j = 0; j < 17; j++) alpha[i*17 + j] *= inv;
        }
        __syncthreads();
        for (int idx = tid; idx < 17*D; idx += blockDim.x) {
            int i = idx / D, d = idx % D;
            float a_ = 0.f;
#pragma unroll
            for (int j = 0; j < 17; j++) a_ += alpha[i*17 + j] * hb[j*D + d];
            accs[idx] += a_;
        }
    }
    __syncthreads();
    int p = g / GPOSE, r = g % GPOSE, b = r / TT, t = r % TT;
    float scale = bn_g[t] * rsqrtf(bn_var[t] + 1e-5f);
    float mu = bn_mean[t], beta = bn_b[t];
    size_t base = ((size_t)(p*BB + b) * TT + t) * FEAT;
    for (int idx = tid; idx < 17*D; idx += blockDim.x) {
        int n = idx / D, d = idx % D;
        float v = accs[idx] * 0.125f + b3[d];
        comb[base + n*D + d] = __float2half((v - mu) * scale + beta);
    }
}

// ---------------- Edge features + FC + BN fold -> half comb ----------------
__global__ void edge_fc_kernel(const float* __restrict__ pose1,
                               const float* __restrict__ pose2,
                               const float* __restrict__ fc_w,
                               const float* __restrict__ fc_b,
                               __half* __restrict__ comb,
                               const float* __restrict__ bn_g,
                               const float* __restrict__ bn_b,
                               const float* __restrict__ bn_mean,
                               const float* __restrict__ bn_var)
{
    __shared__ float feat[76];
    const int g = blockIdx.x;
    const int tid = threadIdx.x;
    int p = g / GPOSE, r = g % GPOSE, b = r / TT, t = r % TT;
    const float* pose = (p == 0 ? pose1 : pose2) + (size_t)r * 17 * 3;
    if (tid < 38) {
        int s = ESRC[tid], d = EDST[tid];
        float vx = pose[d*3 + 0] - pose[s*3 + 0];
        float vy = pose[d*3 + 1] - pose[s*3 + 1];
        feat[2*tid]     = sqrtf(vx*vx + vy*vy);
        feat[2*tid + 1] = atan2f(vy, vx);
    }
    __syncthreads();
    float scale = bn_g[t] * rsqrtf(bn_var[t] + 1e-5f);
    float mu = bn_mean[t], beta = bn_b[t];
    size_t base = ((size_t)(p*BB + b) * TT + t) * FEAT + 17*256;
    if (tid < 128) {
        float s0 = fc_b[tid], s1 = fc_b[tid];
        for (int j = 0; j < 38; j++) {
            float w = fc_w[j*128 + tid];
            s0 += feat[j] * w;
            s1 += feat[38 + j] * w;
        }
        comb[base + tid]       = __float2half((s0 - mu) * scale + beta);
        comb[base + 128 + tid] = __float2half((s1 - mu) * scale + beta);
    }
}

// ---------------- Misc small kernels ----------------
__global__ void bias_sum_kernel(const float* bihf, const float* bhhf,
                                const float* bihb, const float* bhhb)
{
    int i = blockIdx.x * blockDim.x + threadIdx.x;
    if (i < 2048) {
        S_biasf[i] = bihf[i] + bhhf[i];
        S_biasb[i] = bihb[i] + bhhb[i];
    }
}
__global__ void zero_state_kernel()
{
    int i = blockIdx.x * blockDim.x + threadIdx.x;
    if (i < 2*BB*LSTM_H) { S_hst[i] = 0.f; S_cst[i] = 0.f; }
}
__device__ __forceinline__ float sigf(float x) { return 1.f / (1.f + expf(-x)); }

__global__ void lstm_cell_kernel(const float* __restrict__ gates, int gstride,
                                 const float* __restrict__ bias,
                                 float* __restrict__ h, float* __restrict__ c,
                                 float* __restrict__ out_last, int write_last)
{
    int idx = blockIdx.x * blockDim.x + threadIdx.x;
    if (idx >= 2*BB*LSTM_H) return;
    int m = idx / LSTM_H, j = idx % LSTM_H;
    const float* gm = gates + (size_t)m * gstride;
    float gi = gm[j]        + bias[j];
    float gf = gm[512 + j]  + bias[512 + j];
    float gg = gm[1024 + j] + bias[1024 + j];
    float go = gm[1536 + j] + bias[1536 + j];
    float cn = sigf(gf) * c[idx] + sigf(gi) * tanhf(gg);
    float hn = sigf(go) * tanhf(cn);
    c[idx] = cn;
    h[idx] = hn;
    if (write_last) out_last[(size_t)m * (2*LSTM_H) + j] = hn;
}

__global__ void lstm_bcell_kernel(const float* __restrict__ gates,
                                  const float* __restrict__ bias,
                                  float* __restrict__ out)
{
    int idx = blockIdx.x * blockDim.x + threadIdx.x;
    if (idx >= 2*BB*LSTM_H) return;
    int m = idx / LSTM_H, j = idx % LSTM_H;
    const float* gm = gates + (size_t)m * 2048;
    float gi = gm[j]        + bias[j];
    float gg = gm[1024 + j] + bias[1024 + j];
    float go = gm[1536 + j] + bias[1536 + j];
    float cn = sigf(gi) * tanhf(gg);
    out[(size_t)m * (2*LSTM_H) + LSTM_H + j] = sigf(go) * tanhf(cn);
}

// ---------------- Host driver ----------------
extern "C" void kernel_launch(void* const* d_in, const int* in_sizes, int n_in,
                              void* d_out, int out_size)
{
    const float* pose1 = (const float*)d_in[0];
    const float* pose2 = (const float*)d_in[1];
    const float* W1  = (const float*)d_in[3];
    const float* as1 = (const float*)d_in[4];
    const float* ad1 = (const float*)d_in[5];
    const float* b1  = (const float*)d_in[6];
    const float* W2  = (const float*)d_in[7];
    const float* as2 = (const float*)d_in[8];
    const float* ad2 = (const float*)d_in[9];
    const float* b2  = (const float*)d_in[10];
    const float* W3  = (const float*)d_in[11];
    const float* as3 = (const float*)d_in[12];
    const float* ad3 = (const float*)d_in[13];
    const float* b3  = (const float*)d_in[14];
    const float* fc_w = (const float*)d_in[15];
    const float* fc_b = (const float*)d_in[16];
    const float* bn_g = (const float*)d_in[17];
    const float* bn_b = (const float*)d_in[18];
    const float* bn_mean = (const float*)d_in[19];
    const float* bn_var  = (const float*)d_in[20];
    const float* Wih_f = (const float*)d_in[21];
    const float* Whh_f = (const float*)d_in[22];
    const float* bih_f = (const float*)d_in[23];
    const float* bhh_f = (const float*)d_in[24];
    const float* Wih_b = (const float*)d_in[25];
    const float* Whh_b = (const float*)d_in[26];
    const float* bih_b = (const float*)d_in[27];
    const float* bhh_b = (const float*)d_in[28];
    const float* cls_w = (const float*)d_in[29];
    const float* cls_b = (const float*)d_in[30];

    float* out = (float*)d_out;

    float  *g_h, *g_xproj, *g_gates, *g_gatesb, *g_hst, *g_cst, *g_biasf, *g_biasb;
    __half *g_xh, *g_combh, *g_w2t, *g_w3t, *g_wihf, *g_wihb;
    cudaGetSymbolAddress((void**)&g_h, S_h);
    cudaGetSymbolAddress((void**)&g_xh, S_xh);
    cudaGetSymbolAddress((void**)&g_combh, S_combh);
    cudaGetSymbolAddress((void**)&g_xproj, S_xproj);
    cudaGetSymbolAddress((void**)&g_gates, S_gates);
    cudaGetSymbolAddress((void**)&g_gatesb, S_gatesb);
    cudaGetSymbolAddress((void**)&g_hst, S_hst);
    cudaGetSymbolAddress((void**)&g_cst, S_cst);
    cudaGetSymbolAddress((void**)&g_biasf, S_biasf);
    cudaGetSymbolAddress((void**)&g_biasb, S_biasb);
    cudaGetSymbolAddress((void**)&g_w2t, S_w2t);
    cudaGetSymbolAddress((void**)&g_w3t, S_w3t);
    cudaGetSymbolAddress((void**)&g_wihf, S_wihf);
    cudaGetSymbolAddress((void**)&g_wihb, S_wihb);

    // ---- weight conversions (once per launch, ~0.1ms) ----
    transpose_h_kernel<<<dim3(1024/32, 512/32), dim3(32, 8)>>>(W2, g_w2t, 512, 1024);
    transpose_h_kernel<<<dim3(2048/32, 1024/32), dim3(32, 8)>>>(W3, g_w3t, 1024, 2048);
    f2h_kernel<<<1024, 256>>>(Wih_f, g_wihf, (size_t)2048 * FEAT);
    f2h_kernel<<<1024, 256>>>(Wih_b, g_wihb, (size_t)2048 * FEAT);

    // ---- GAT layer 1 (K=3, fp32) ----
    {
        dim3 grid(cdiv(512, 128), cdiv(ROWS_POSE, 128));
        sgemm_kernel<128,128,8,8,8,0><<<grid, 256>>>(
            ROWS_POSE, 512, 3, pose1, 3, W1, 512, g_h, 512, nullptr, nullptr, 0);
        sgemm_kernel<128,128,8,8,8,0><<<grid, 256>>>(
            ROWS_POSE, 512, 3, pose2, 3, W1, 512, g_h + (size_t)ROWS_POSE*512, 512,
            nullptr, nullptr, 0);
    }
    gat_attn_concat<64><<<GTOT*HEADS, 128>>>(g_h, as1, ad1, b1, g_xh, 512);

    // ---- GAT layer 2: fp16 tensor cores (104448 x 1024 x 512) ----
    hgemm_tn<<<dim3(1024/128, ROWS_TOT/128), 256>>>(
        ROWS_TOT, 1024, 512, g_xh, 512, g_w2t, 512, g_h, 1024);
    gat_attn_concat<128><<<GTOT*HEADS, 128>>>(g_h, as2, ad2, b2, g_xh, 1024);

    // ---- GAT layer 3: fp16 (104448 x 2048 x 1024) ----
    hgemm_tn<<<dim3(2048/128, ROWS_TOT/128), 256>>>(
        ROWS_TOT, 2048, 1024, g_xh, 1024, g_w3t, 1024, g_h, 2048);
    gat_attn_mean<<<GTOT, 256>>>(g_h, as3, ad3, b3, g_combh,
                                 bn_g, bn_b, bn_mean, bn_var);

    // ---- edge features + FC (BN folded) ----
    edge_fc_kernel<<<GTOT, 128>>>(pose1, pose2, fc_w, fc_b, g_combh,
                                  bn_g, bn_b, bn_mean, bn_var);

    // ---- gate biases ----
    bias_sum_kernel<<<8, 256>>>(bih_f, bhh_f, bih_b, bhh_b);

    // ---- forward input projection: fp16 (6144 x 2048 x 4608) ----
    hgemm_tn<<<dim3(2048/128, (2*BB*TT)/128), 256>>>(
        2*BB*TT, 2048, FEAT, g_combh, FEAT, g_wihf, FEAT, g_xproj, 2048);

    // ---- backward single step at t=23: fp16 (256 x 2048 x 4608) ----
    hgemm_tn<<<dim3(2048/128, 2), 256>>>(
        2*BB, 2048, FEAT, g_combh + (size_t)23*FEAT, TT*FEAT, g_wihb, FEAT,
        g_gatesb, 2048);
    lstm_bcell_kernel<<<cdiv(2*BB*LSTM_H, 256), 256>>>(g_gatesb, g_biasb, out);

    // ---- forward recurrence (fp32) ----
    zero_state_kernel<<<cdiv(2*BB*LSTM_H, 256), 256>>>();
    lstm_cell_kernel<<<cdiv(2*BB*LSTM_H, 256), 256>>>(
        g_xproj, TT*2048, g_biasf, g_hst, g_cst, out, 0);
    for (int t = 1; t < TT; t++) {
        dim3 grid(cdiv(2048, 64), cdiv(2*BB, 64));
        sgemm_kernel<64,64,8,4,4,1><<<grid, 256>>>(
            2*BB, 2048, LSTM_H, g_hst, LSTM_H, Whh_f, LSTM_H,
            g_gates, 2048, nullptr, g_xproj + (size_t)t*2048, TT*2048);
        lstm_cell_kernel<<<cdiv(2*BB*LSTM_H, 256), 256>>>(
            g_gates, 2048, g_biasf, g_hst, g_cst, out, (t == TT-1) ? 1 : 0);
    }

    // ---- classifier (fp32) ----
    {
        dim3 grid(cdiv(NCLS, 64), cdiv(2*BB, 64));
        sgemm_kernel<64,64,8,4,4,0><<<grid, 256>>>(
            2*BB, NCLS, 2*LSTM_H, out, 2*LSTM_H, cls_w, NCLS,
            out + OUT_LSTM, NCLS, cls_b, nullptr, 0);
    }
}

// round 14
// speedup vs baseline: 3.0684x; 1.2689x over previous
#include <cuda_runtime.h>
#include <cuda_fp16.h>
#include <mma.h>
#include <math.h>
#include <stdint.h>

using namespace nvcuda;

// ---------------- Problem constants ----------------
#define NN_NODES 17
#define HEADS 8
#define BB 128
#define TT 24
#define GPOSE 3072
#define GTOT 6144
#define ROWS_TOT (GTOT*NN_NODES)      // 104448 = 816*128
#define ROWS_POSE (GPOSE*NN_NODES)    // 52224
#define FEAT 4608
#define LSTM_H 512
#define NCLS 500
#define OUT_LSTM (2*BB*2*LSTM_H)

// ---------------- Scratch (static device memory; no allocs) ----------------
__device__ float  S_h1[(size_t)ROWS_TOT * 512];         // L1 GEMM out (fp32)
__device__ __half S_hbig[(size_t)ROWS_TOT * 2048];      // L2 out (ld 1024) then L3 out (ld 2048)
__device__ __half S_xh[(size_t)ROWS_TOT * 1024];        // post-attn activations (GEMM A)
__device__ __half S_combh[(size_t)(2*BB) * TT * FEAT];  // half comb (GEMM A)
__device__ float  S_xproj[(size_t)(2*BB) * TT * 2048];
__device__ float  S_gates[(size_t)(2*BB) * 2048];
__device__ float  S_gatesb[(size_t)(2*BB) * 2048];
__device__ __half S_hh[(size_t)(2*BB) * LSTM_H];        // LSTM h state (half, GEMM A)
__device__ float  S_cst[(size_t)(2*BB) * LSTM_H];
__device__ float  S_biasf[2048];
__device__ float  S_biasb[2048];
__device__ __half S_w2t[(size_t)1024 * 512];    // W2^T  [1024,512] half
__device__ __half S_w3t[(size_t)2048 * 1024];   // W3^T  [2048,1024] half
__device__ __half S_wihf[(size_t)2048 * FEAT];  // Wih_f half
__device__ __half S_wihb[(size_t)2048 * FEAT];  // Wih_b half
__device__ __half S_whhh[(size_t)2048 * LSTM_H];// Whh_f half [2048,512]

__constant__ unsigned int ADJMASK[17] = {
    0x7u, 0xFu, 0x17u, 0x2Au, 0x54u, 0x8E8u, 0x1170u, 0x2A0u, 0x540u,
    0x280u, 0x500u, 0x3820u, 0x5840u, 0xA800u, 0x15000u, 0xA000u, 0x14000u
};
__constant__ int ESRC[38] = {15,13,16,14,11,5,6,5,5,6,7,8,1,0,0,1,2,3,4,
                             13,11,14,12,12,11,12,6,7,8,9,10,2,1,2,3,4,5,6};
__constant__ int EDST[38] = {13,11,14,12,12,11,12,6,7,8,9,10,2,1,2,3,4,5,6,
                             15,13,16,14,11,5,6,5,5,6,7,8,1,0,0,1,2,3,4};

static inline int cdiv(int a, int b) { return (a + b - 1) / b; }

// =======================================================================
// fp16 wmma GEMM (TN): C[M,N] = A[M,K](half,row) * B[N,K](half,row)^T
// HC=false: C fp32.  HC=true: C half (fragment staged through smem).
// BM=BN=128, BK=32, 256 threads, 2-stage cp.async double buffering.
// Requires M%128==0, N%128==0, K%32==0, lda/ldb/ldc %8==0.
// =======================================================================
__device__ __forceinline__ uint32_t smem_u32h(const void* p) {
    return (uint32_t)__cvta_generic_to_shared(p);
}
__device__ __forceinline__ void cpasync16h(uint32_t dst, const void* src) {
    asm volatile("cp.async.cg.shared.global [%0], [%1], 16;" :: "r"(dst), "l"(src));
}

template<bool HC>
__global__ void __launch_bounds__(256, 2) hgemm_tn(
    int M, int N, int K,
    const __half* __restrict__ A, int lda,
    const __half* __restrict__ B, int ldb,
    void* __restrict__ Cv, int ldc)
{
    __shared__ __align__(16) __half As[2][128][40];
    __shared__ __align__(16) __half Bs[2][128][40];
    const int tid  = threadIdx.x;
    const int warp = tid >> 5;
    const int wm   = warp & 3;      // 32-row strip
    const int wn   = warp >> 2;     // 64-col strip
    const int bm   = blockIdx.y * 128;
    const int bn   = blockIdx.x * 128;
    const int T    = K >> 5;

    wmma::fragment<wmma::accumulator, 16, 16, 16, float> acc[2][4];
#pragma unroll
    for (int i = 0; i < 2; i++)
#pragma unroll
        for (int j = 0; j < 4; j++) wmma::fill_fragment(acc[i][j], 0.0f);

    const uint32_t as_base = smem_u32h(&As[0][0][0]);
    const uint32_t bs_base = smem_u32h(&Bs[0][0][0]);
    const uint32_t stage_bytes = 128 * 40 * 2;   // 10240

    auto load_stage = [&](int s, int kt) {
        const __half* a = A + (size_t)bm * lda + kt * 32;
        const __half* b = B + (size_t)bn * ldb + kt * 32;
#pragma unroll
        for (int i = 0; i < 2; i++) {
            int q = tid + i * 256;           // 0..511
            int row = q >> 2, c = q & 3;     // c*8 halves = 16B
            cpasync16h(as_base + s * stage_bytes + row * 80 + c * 16,
                       a + (size_t)row * lda + c * 8);
        }
#pragma unroll
        for (int i = 0; i < 2; i++) {
            int q = tid + i * 256;
            int row = q >> 2, c = q & 3;
            cpasync16h(bs_base + s * stage_bytes + row * 80 + c * 16,
                       b + (size_t)row * ldb + c * 8);
        }
    };

    load_stage(0, 0);
    asm volatile("cp.async.commit_group;" ::: "memory");

    for (int kt = 0; kt < T; kt++) {
        const int s = kt & 1;
        if (kt + 1 < T) {
            load_stage(s ^ 1, kt + 1);
            asm volatile("cp.async.commit_group;" ::: "memory");
            asm volatile("cp.async.wait_group 1;" ::: "memory");
        } else {
            asm volatile("cp.async.wait_group 0;" ::: "memory");
        }
        __syncthreads();

#pragma unroll
        for (int kk = 0; kk < 32; kk += 16) {
            wmma::fragment<wmma::matrix_a, 16, 16, 16, __half, wmma::row_major> af[2];
            wmma::load_matrix_sync(af[0], &As[s][wm * 32][kk], 40);
            wmma::load_matrix_sync(af[1], &As[s][wm * 32 + 16][kk], 40);
#pragma unroll
            for (int j = 0; j < 4; j++) {
                wmma::fragment<wmma::matrix_b, 16, 16, 16, __half, wmma::col_major> bf;
                wmma::load_matrix_sync(bf, &Bs[s][wn * 64 + j * 16][kk], 40);
                wmma::mma_sync(acc[0][j], af[0], bf, acc[0][j]);
                wmma::mma_sync(acc[1][j], af[1], bf, acc[1][j]);
            }
        }
        __syncthreads();
    }

    if (!HC) {
        float* C = (float*)Cv;
#pragma unroll
        for (int i = 0; i < 2; i++)
#pragma unroll
            for (int j = 0; j < 4; j++)
                wmma::store_matrix_sync(
                    &C[(size_t)(bm + wm * 32 + i * 16) * ldc + bn + wn * 64 + j * 16],
                    acc[i][j], ldc, wmma::mem_row_major);
    } else {
        // stage fragments through smem (reuse drained As region) -> half C
        __half* Ch = (__half*)Cv;
        float* stg = reinterpret_cast<float*>(&As[0][0][0]) + warp * (16 * 24);
        const int lane = tid & 31;
        const int r  = lane >> 1;
        const int c0 = (lane & 1) * 8;
#pragma unroll
        for (int i = 0; i < 2; i++)
#pragma unroll
            for (int j = 0; j < 4; j++) {
                __syncwarp();
                wmma::store_matrix_sync(stg, acc[i][j], 24, wmma::mem_row_major);
                __syncwarp();
                __half2 h2[4];
#pragma unroll
                for (int q = 0; q < 4; q++)
                    h2[q] = __floats2half2_rn(stg[r * 24 + c0 + 2 * q],
                                              stg[r * 24 + c0 + 2 * q + 1]);
                size_t grow = (size_t)(bm + wm * 32 + i * 16 + r);
                size_t gcol = (size_t)(bn + wn * 64 + j * 16 + c0);
                *reinterpret_cast<uint4*>(&Ch[grow * ldc + gcol]) =
                    *reinterpret_cast<uint4*>(h2);
            }
    }
}

// ---------------- weight conversion kernels ----------------
__global__ void f2h_kernel(const float* __restrict__ in, __half* __restrict__ out, size_t n)
{
    for (size_t i = (size_t)blockIdx.x * blockDim.x + threadIdx.x; i < n;
         i += (size_t)gridDim.x * blockDim.x)
        out[i] = __float2half(in[i]);
}

__global__ void transpose_h_kernel(const float* __restrict__ in, __half* __restrict__ out,
                                   int R, int Ccols)
{
    __shared__ float t[32][33];
    int bx = blockIdx.x * 32, by = blockIdx.y * 32;
#pragma unroll
    for (int dy = 0; dy < 32; dy += 8) {
        int r = by + threadIdx.y + dy, c = bx + threadIdx.x;
        if (r < R && c < Ccols) t[threadIdx.y + dy][threadIdx.x] = in[(size_t)r * Ccols + c];
    }
    __syncthreads();
#pragma unroll
    for (int dy = 0; dy < 32; dy += 8) {
        int r = bx + threadIdx.y + dy, c = by + threadIdx.x;
        if (r < Ccols && c < R) out[(size_t)r * R + c] = __float2half(t[threadIdx.x][threadIdx.y + dy]);
    }
}

// ---------------- fp32 GEMM (small/odd shapes) ----------------
template<int BM, int BN, int BK, int TM, int TN, int TB>
__global__ void sgemm_kernel(int M, int N, int K,
                             const float* __restrict__ A, int lda,
                             const float* __restrict__ B, int ldb,
                             float* __restrict__ C, int ldc,
                             const float* __restrict__ bias,
                             const float* __restrict__ addmat, int ldadd)
{
    constexpr int THREADS = (BM/TM) * (BN/TN);
    __shared__ float As[BK][BM];
    __shared__ float Bs[BK][BN];
    const int tid = threadIdx.x;
    const int bm = blockIdx.y * BM;
    const int bn = blockIdx.x * BN;
    const int tx = tid % (BN/TN);
    const int ty = tid / (BN/TN);

    float acc[TM][TN];
#pragma unroll
    for (int i = 0; i < TM; i++)
#pragma unroll
        for (int j = 0; j < TN; j++) acc[i][j] = 0.f;

    for (int k0 = 0; k0 < K; k0 += BK) {
        for (int i = tid; i < BM*BK; i += THREADS) {
            int m = i / BK, k = i % BK;
            int gm = bm + m, gk = k0 + k;
            As[k][m] = (gm < M && gk < K) ? A[(size_t)gm * lda + gk] : 0.f;
        }
        if (TB == 0) {
            for (int i = tid; i < BK*BN; i += THREADS) {
                int k = i / BN, n = i % BN;
                int gk = k0 + k, gn = bn + n;
                Bs[k][n] = (gk < K && gn < N) ? B[(size_t)gk * ldb + gn] : 0.f;
            }
        } else {
            for (int i = tid; i < BK*BN; i += THREADS) {
                int n = i / BK, k = i % BK;
                int gk = k0 + k, gn = bn + n;
                Bs[k][n] = (gk < K && gn < N) ? B[(size_t)gn * ldb + gk] : 0.f;
            }
        }
        __syncthreads();
#pragma unroll
        for (int k = 0; k < BK; k++) {
            float ra[TM], rb[TN];
#pragma unroll
            for (int i = 0; i < TM; i++) ra[i] = As[k][ty*TM + i];
#pragma unroll
            for (int j = 0; j < TN; j++) rb[j] = Bs[k][tx*TN + j];
#pragma unroll
            for (int i = 0; i < TM; i++)
#pragma unroll
                for (int j = 0; j < TN; j++) acc[i][j] += ra[i] * rb[j];
        }
        __syncthreads();
    }

#pragma unroll
    for (int i = 0; i < TM; i++) {
        int gm = bm + ty*TM + i;
        if (gm >= M) continue;
#pragma unroll
        for (int j = 0; j < TN; j++) {
            int gn = bn + tx*TN + j;
            if (gn >= N) continue;
            float v = acc[i][j];
            if (bias)   v += bias[gn];
            if (addmat) v += addmat[(size_t)gm * ldadd + gn];
            C[(size_t)gm * ldc + gn] = v;
        }
    }
}

// ---------------- GAT attention (concat layers 1&2) -> half output ----------------
template<int D, typename IT>
__global__ void gat_attn_concat(const IT* __restrict__ h,
                                const float* __restrict__ a_src,
                                const float* __restrict__ a_dst,
                                const float* __restrict__ bias,
                                __half* __restrict__ out, int ld)
{
    __shared__ float hb[17*D];
    __shared__ float ss[17], sd[17];
    __shared__ float alpha[17*17];
    const int g = blockIdx.x >> 3;
    const int head = blockIdx.x & 7;
    const int tid = threadIdx.x;

    for (int idx = tid; idx < 17*D; idx += blockDim.x) {
        int n = idx / D, d = idx % D;
        hb[idx] = (float)h[(size_t)(g*17 + n) * ld + head*D + d];
    }
    __syncthreads();
    if (tid < 34) {
        int n = tid % 17;
        const float* a = (tid < 17 ? a_src : a_dst) + head*D;
        float s = 0.f;
        for (int d = 0; d < D; d++) s += hb[n*D + d] * a[d];
        if (tid < 17) ss[n] = s; else sd[n] = s;
    }
    __syncthreads();
    if (tid < 17) {
        int i = tid;
        unsigned m = ADJMASK[i];
        float ev[17];
        float mx = -1e30f;
#pragma unroll
        for (int j = 0; j < 17; j++) {
            if ((m >> j) & 1u) {
                float e = sd[i] + ss[j];
                e = e > 0.f ? e : 0.2f * e;
                ev[j] = e;
                if (e > mx) mx = e;
            }
        }
        float sum = 0.f;
#pragma unroll
        for (int j = 0; j < 17; j++) {
            float a_ = 0.f;
            if ((m >> j) & 1u) { a_ = expf(ev[j] - mx); sum += a_; }
            alpha[i*17 + j] = a_;
        }
        float inv = 1.f / sum;
#pragma unroll
        for (int j = 0; j < 17; j++) alpha[i*17 + j] *= inv;
    }
    __syncthreads();
    for (int idx = tid; idx < 17*D; idx += blockDim.x) {
        int i = idx / D, d = idx % D;
        float accv = 0.f;
#pragma unroll
        for (int j = 0; j < 17; j++) accv += alpha[i*17 + j] * hb[j*D + d];
        float v = accv + bias[head*D + d];
        v = v > 0.f ? v : expm1f(v);           // ELU
        out[(size_t)(g*17 + i) * ld + head*D + d] = __float2half(v);
    }
}

// ---------------- GAT layer 3 (mean heads) + BN fold -> half comb ----------------
__global__ void gat_attn_mean(const __half* __restrict__ h,
                              const float* __restrict__ a_src,
                              const float* __restrict__ a_dst,
                              const float* __restrict__ b3,
                              __half* __restrict__ comb,
                              const float* __restrict__ bn_g,
                              const float* __restrict__ bn_b,
                              const float* __restrict__ bn_mean,
                              const float* __restrict__ bn_var)
{
    const int D = 256;
    __shared__ float hb[17*256];
    __shared__ float accs[17*256];
    __shared__ float ss[17], sd[17];
    __shared__ float alpha[17*17];
    const int g = blockIdx.x;
    const int tid = threadIdx.x;

    for (int idx = tid; idx < 17*D; idx += blockDim.x) accs[idx] = 0.f;

    for (int head = 0; head < 8; head++) {
        __syncthreads();
        for (int idx = tid; idx < 17*D; idx += blockDim.x) {
            int n = idx / D, d = idx % D;
            hb[idx] = __half2float(h[(size_t)(g*17 + n) * 2048 + head*D + d]);
        }
        __syncthreads();
        if (tid < 34) {
            int n = tid % 17;
            const float* a = (tid < 17 ? a_src : a_dst) + head*D;
            float s = 0.f;
            for (int d = 0; d < D; d++) s += hb[n*D + d] * a[d];
            if (tid < 17) ss[n] = s; else sd[n] = s;
        }
        __syncthreads();
        if (tid < 17) {
            int i = tid;
            unsigned m = ADJMASK[i];
            float ev[17];
            float mx = -1e30f;
#pragma unroll
            for (int j = 0; j < 17; j++) {
                if ((m >> j) & 1u) {
                    float e = sd[i] + ss[j];
                    e = e > 0.f ? e : 0.2f * e;
                    ev[j] = e;
                    if (e > mx) mx = e;
                }
            }
            float sum = 0.f;
#pragma unroll
            for (int j = 0; j < 17; j++) {
                float a_ = 0.f;
                if ((m >> j) & 1u) { a_ = expf(ev[j] - mx); sum += a_; }
                alpha[i*17 + j] = a_;
            }
            float inv = 1.f / sum;
#pragma unroll
            for (int j = 0; j < 17; j++) alpha[i*17 + j] *= inv;
        }
        __syncthreads();
        for (int idx = tid; idx < 17*D; idx += blockDim.x) {
            int i = idx / D, d = idx % D;
            float a_ = 0.f;
#pragma unroll
            for (int j = 0; j < 17; j++) a_ += alpha[i*17 + j] * hb[j*D + d];
            accs[idx] += a_;
        }
    }
    __syncthreads();
    int p = g / GPOSE, r = g % GPOSE, b = r / TT, t = r % TT;
    float scale = bn_g[t] * rsqrtf(bn_var[t] + 1e-5f);
    float mu = bn_mean[t], beta = bn_b[t];
    size_t base = ((size_t)(p*BB + b) * TT + t) * FEAT;
    for (int idx = tid; idx < 17*D; idx += blockDim.x) {
        int n = idx / D, d = idx % D;
        float v = accs[idx] * 0.125f + b3[d];
        comb[base + n*D + d] = __float2half((v - mu) * scale + beta);
    }
}

// ---------------- Edge features + FC + BN fold -> half comb ----------------
__global__ void edge_fc_kernel(const float* __restrict__ pose1,
                               const float* __restrict__ pose2,
                               const float* __restrict__ fc_w,
                               const float* __restrict__ fc_b,
                               __half* __restrict__ comb,
                               const float* __restrict__ bn_g,
                               const float* __restrict__ bn_b,
                               const float* __restrict__ bn_mean,
                               const float* __restrict__ bn_var)
{
    __shared__ float feat[76];
    const int g = blockIdx.x;
    const int tid = threadIdx.x;
    int p = g / GPOSE, r = g % GPOSE, b = r / TT, t = r % TT;
    const float* pose = (p == 0 ? pose1 : pose2) + (size_t)r * 17 * 3;
    if (tid < 38) {
        int s = ESRC[tid], d = EDST[tid];
        float vx = pose[d*3 + 0] - pose[s*3 + 0];
        float vy = pose[d*3 + 1] - pose[s*3 + 1];
        feat[2*tid]     = sqrtf(vx*vx + vy*vy);
        feat[2*tid + 1] = atan2f(vy, vx);
    }
    __syncthreads();
    float scale = bn_g[t] * rsqrtf(bn_var[t] + 1e-5f);
    float mu = bn_mean[t], beta = bn_b[t];
    size_t base = ((size_t)(p*BB + b) * TT + t) * FEAT + 17*256;
    if (tid < 128) {
        float s0 = fc_b[tid], s1 = fc_b[tid];
        for (int j = 0; j < 38; j++) {
            float w = fc_w[j*128 + tid];
            s0 += feat[j] * w;
            s1 += feat[38 + j] * w;
        }
        comb[base + tid]       = __float2half((s0 - mu) * scale + beta);
        comb[base + 128 + tid] = __float2half((s1 - mu) * scale + beta);
    }
}

// ---------------- Misc small kernels ----------------
__global__ void bias_sum_kernel(const float* bihf, const float* bhhf,
                                const float* bihb, const float* bhhb)
{
    int i = blockIdx.x * blockDim.x + threadIdx.x;
    if (i < 2048) {
        S_biasf[i] = bihf[i] + bhhf[i];
        S_biasb[i] = bihb[i] + bhhb[i];
    }
}
__global__ void zero_state_kernel()
{
    int i = blockIdx.x * blockDim.x + threadIdx.x;
    if (i < 2*BB*LSTM_H) { S_cst[i] = 0.f; S_hh[i] = __float2half(0.f); }
}
__device__ __forceinline__ float sigf(float x) { return 1.f / (1.f + expf(-x)); }

// cell: gates = (hh? hh:0) + xproj_t + bias; writes c (f32), h (half), optional last-h (f32)
__global__ void lstm_cell2(const float* __restrict__ hh,
                           const float* __restrict__ xp, int xstride,
                           const float* __restrict__ bias,
                           float* __restrict__ c, __half* __restrict__ hhalf,
                           float* __restrict__ out_last, int write_last)
{
    int idx = blockIdx.x * blockDim.x + threadIdx.x;
    if (idx >= 2*BB*LSTM_H) return;
    int m = idx / LSTM_H, j = idx % LSTM_H;
    const float* x = xp + (size_t)m * xstride;
    float gi = x[j]        + bias[j];
    float gf = x[512 + j]  + bias[512 + j];
    float gg = x[1024 + j] + bias[1024 + j];
    float go = x[1536 + j] + bias[1536 + j];
    if (hh) {
        const float* hm = hh + (size_t)m * 2048;
        gi += hm[j]; gf += hm[512 + j]; gg += hm[1024 + j]; go += hm[1536 + j];
    }
    float cn = sigf(gf) * c[idx] + sigf(gi) * tanhf(gg);
    float hn = sigf(go) * tanhf(cn);
    c[idx] = cn;
    hhalf[idx] = __float2half(hn);
    if (write_last) out_last[(size_t)m * (2*LSTM_H) + j] = hn;
}

__global__ void lstm_bcell_kernel(const float* __restrict__ gates,
                                  const float* __restrict__ bias,
                                  float* __restrict__ out)
{
    int idx = blockIdx.x * blockDim.x + threadIdx.x;
    if (idx >= 2*BB*LSTM_H) return;
    int m = idx / LSTM_H, j = idx % LSTM_H;
    const float* gm = gates + (size_t)m * 2048;
    float gi = gm[j]        + bias[j];
    float gg = gm[1024 + j] + bias[1024 + j];
    float go = gm[1536 + j] + bias[1536 + j];
    float cn = sigf(gi) * tanhf(gg);
    out[(size_t)m * (2*LSTM_H) + LSTM_H + j] = sigf(go) * tanhf(cn);
}

// ---------------- Host driver ----------------
extern "C" void kernel_launch(void* const* d_in, const int* in_sizes, int n_in,
                              void* d_out, int out_size)
{
    const float* pose1 = (const float*)d_in[0];
    const float* pose2 = (const float*)d_in[1];
    const float* W1  = (const float*)d_in[3];
    const float* as1 = (const float*)d_in[4];
    const float* ad1 = (const float*)d_in[5];
    const float* b1  = (const float*)d_in[6];
    const float* W2  = (const float*)d_in[7];
    const float* as2 = (const float*)d_in[8];
    const float* ad2 = (const float*)d_in[9];
    const float* b2  = (const float*)d_in[10];
    const float* W3  = (const float*)d_in[11];
    const float* as3 = (const float*)d_in[12];
    const float* ad3 = (const float*)d_in[13];
    const float* b3  = (const float*)d_in[14];
    const float* fc_w = (const float*)d_in[15];
    const float* fc_b = (const float*)d_in[16];
    const float* bn_g = (const float*)d_in[17];
    const float* bn_b = (const float*)d_in[18];
    const float* bn_mean = (const float*)d_in[19];
    const float* bn_var  = (const float*)d_in[20];
    const float* Wih_f = (const float*)d_in[21];
    const float* Whh_f = (const float*)d_in[22];
    const float* bih_f = (const float*)d_in[23];
    const float* bhh_f = (const float*)d_in[24];
    const float* Wih_b = (const float*)d_in[25];
    const float* Whh_b = (const float*)d_in[26];
    const float* bih_b = (const float*)d_in[27];
    const float* bhh_b = (const float*)d_in[28];
    const float* cls_w = (const float*)d_in[29];
    const float* cls_b = (const float*)d_in[30];

    float* out = (float*)d_out;

    float  *g_h1, *g_xproj, *g_gates, *g_gatesb, *g_cst, *g_biasf, *g_biasb;
    __half *g_hbig, *g_xh, *g_combh, *g_hh, *g_w2t, *g_w3t, *g_wihf, *g_wihb, *g_whhh;
    cudaGetSymbolAddress((void**)&g_h1, S_h1);
    cudaGetSymbolAddress((void**)&g_hbig, S_hbig);
    cudaGetSymbolAddress((void**)&g_xh, S_xh);
    cudaGetSymbolAddress((void**)&g_combh, S_combh);
    cudaGetSymbolAddress((void**)&g_xproj, S_xproj);
    cudaGetSymbolAddress((void**)&g_gates, S_gates);
    cudaGetSymbolAddress((void**)&g_gatesb, S_gatesb);
    cudaGetSymbolAddress((void**)&g_hh, S_hh);
    cudaGetSymbolAddress((void**)&g_cst, S_cst);
    cudaGetSymbolAddress((void**)&g_biasf, S_biasf);
    cudaGetSymbolAddress((void**)&g_biasb, S_biasb);
    cudaGetSymbolAddress((void**)&g_w2t, S_w2t);
    cudaGetSymbolAddress((void**)&g_w3t, S_w3t);
    cudaGetSymbolAddress((void**)&g_wihf, S_wihf);
    cudaGetSymbolAddress((void**)&g_wihb, S_wihb);
    cudaGetSymbolAddress((void**)&g_whhh, S_whhh);

    // ---- weight conversions (once per launch) ----
    transpose_h_kernel<<<dim3(1024/32, 512/32), dim3(32, 8)>>>(W2, g_w2t, 512, 1024);
    transpose_h_kernel<<<dim3(2048/32, 1024/32), dim3(32, 8)>>>(W3, g_w3t, 1024, 2048);
    f2h_kernel<<<1024, 256>>>(Wih_f, g_wihf, (size_t)2048 * FEAT);
    f2h_kernel<<<1024, 256>>>(Wih_b, g_wihb, (size_t)2048 * FEAT);
    f2h_kernel<<<512, 256>>>(Whh_f, g_whhh, (size_t)2048 * LSTM_H);

    // ---- GAT layer 1 (K=3, fp32) ----
    {
        dim3 grid(cdiv(512, 128), cdiv(ROWS_POSE, 128));
        sgemm_kernel<128,128,8,8,8,0><<<grid, 256>>>(
            ROWS_POSE, 512, 3, pose1, 3, W1, 512, g_h1, 512, nullptr, nullptr, 0);
        sgemm_kernel<128,128,8,8,8,0><<<grid, 256>>>(
            ROWS_POSE, 512, 3, pose2, 3, W1, 512, g_h1 + (size_t)ROWS_POSE*512, 512,
            nullptr, nullptr, 0);
    }
    gat_attn_concat<64, float><<<GTOT*HEADS, 128>>>(g_h1, as1, ad1, b1, g_xh, 512);

    // ---- GAT layer 2: fp16 TC (104448 x 1024 x 512), half C ----
    hgemm_tn<true><<<dim3(1024/128, ROWS_TOT/128), 256>>>(
        ROWS_TOT, 1024, 512, g_xh, 512, g_w2t, 512, g_hbig, 1024);
    gat_attn_concat<128, __half><<<GTOT*HEADS, 128>>>(g_hbig, as2, ad2, b2, g_xh, 1024);

    // ---- GAT layer 3: fp16 (104448 x 2048 x 1024), half C ----
    hgemm_tn<true><<<dim3(2048/128, ROWS_TOT/128), 256>>>(
        ROWS_TOT, 2048, 1024, g_xh, 1024, g_w3t, 1024, g_hbig, 2048);
    gat_attn_mean<<<GTOT, 256>>>(g_hbig, as3, ad3, b3, g_combh,
                                 bn_g, bn_b, bn_mean, bn_var);

    // ---- edge features + FC (BN folded) ----
    edge_fc_kernel<<<GTOT, 128>>>(pose1, pose2, fc_w, fc_b, g_combh,
                                  bn_g, bn_b, bn_mean, bn_var);

    // ---- gate biases ----
    bias_sum_kernel<<<8, 256>>>(bih_f, bhh_f, bih_b, bhh_b);

    // ---- forward input projection: fp16 (6144 x 2048 x 4608), fp32 C ----
    hgemm_tn<false><<<dim3(2048/128, (2*BB*TT)/128), 256>>>(
        2*BB*TT, 2048, FEAT, g_combh, FEAT, g_wihf, FEAT, g_xproj, 2048);

    // ---- backward single step at t=23: fp16 (256 x 2048 x 4608) ----
    hgemm_tn<false><<<dim3(2048/128, 2), 256>>>(
        2*BB, 2048, FEAT, g_combh + (size_t)23*FEAT, TT*FEAT, g_wihb, FEAT,
        g_gatesb, 2048);
    lstm_bcell_kernel<<<cdiv(2*BB*LSTM_H, 256), 256>>>(g_gatesb, g_biasb, out);

    // ---- forward recurrence: fp16 TC hh-GEMM per step ----
    zero_state_kernel<<<cdiv(2*BB*LSTM_H, 256), 256>>>();
    lstm_cell2<<<cdiv(2*BB*LSTM_H, 256), 256>>>(
        nullptr, g_xproj, TT*2048, g_biasf, g_cst, g_hh, out, 0);
    for (int t = 1; t < TT; t++) {
        hgemm_tn<false><<<dim3(2048/128, 2), 256>>>(
            2*BB, 2048, LSTM_H, g_hh, LSTM_H, g_whhh, LSTM_H, g_gates, 2048);
        lstm_cell2<<<cdiv(2*BB*LSTM_H, 256), 256>>>(
            g_gates, g_xproj + (size_t)t*2048, TT*2048, g_biasf, g_cst, g_hh,
            out, (t == TT-1) ? 1 : 0);
    }

    // ---- classifier (fp32) ----
    {
        dim3 grid(cdiv(NCLS, 64), cdiv(2*BB, 64));
        sgemm_kernel<64,64,8,4,4,0><<<grid, 256>>>(
            2*BB, NCLS, 2*LSTM_H, out, 2*LSTM_H, cls_w, NCLS,
            out + OUT_LSTM, NCLS, cls_b, nullptr, 0);
    }
}

// round 16
// speedup vs baseline: 3.6731x; 1.1971x over previous
#include <cuda_runtime.h>
#include <cuda_fp16.h>
#include <mma.h>
#include <math.h>
#include <stdint.h>

using namespace nvcuda;

// ---------------- Problem constants ----------------
#define NN_NODES 17
#define HEADS 8
#define BB 128
#define TT 24
#define GPOSE 3072
#define GTOT 6144
#define ROWS_TOT (GTOT*NN_NODES)      // 104448 = 816*128
#define ROWS_POSE (GPOSE*NN_NODES)    // 52224
#define FEAT 4608
#define LSTM_H 512
#define NCLS 500
#define OUT_LSTM (2*BB*2*LSTM_H)

// ---------------- Scratch (static device memory; no allocs) ----------------
__device__ __half S_hbig[(size_t)ROWS_TOT * 2048];      // L2 out (ld 1024) then L3 out (ld 2048)
__device__ __half S_xh[(size_t)ROWS_TOT * 1024];        // post-attn activations (GEMM A)
__device__ __half S_combh[(size_t)(2*BB) * TT * FEAT];  // half comb (GEMM A)
__device__ float  S_xproj[(size_t)(2*BB) * TT * 2048];
__device__ float  S_gates[(size_t)(2*BB) * 2048];
__device__ float  S_gatesb[(size_t)(2*BB) * 2048];
__device__ __half S_hh[(size_t)(2*BB) * LSTM_H];        // LSTM h state (half, GEMM A)
__device__ float  S_cst[(size_t)(2*BB) * LSTM_H];
__device__ float  S_biasf[2048];
__device__ float  S_biasb[2048];
__device__ __half S_w2t[(size_t)1024 * 512];    // W2^T  [1024,512] half
__device__ __half S_w3t[(size_t)2048 * 1024];   // W3^T  [2048,1024] half
__device__ __half S_wihf[(size_t)2048 * FEAT];  // Wih_f half
__device__ __half S_wihb[(size_t)2048 * FEAT];  // Wih_b half
__device__ __half S_whhh[(size_t)2048 * LSTM_H];// Whh_f half [2048,512]

__constant__ unsigned int ADJMASK[17] = {
    0x7u, 0xFu, 0x17u, 0x2Au, 0x54u, 0x8E8u, 0x1170u, 0x2A0u, 0x540u,
    0x280u, 0x500u, 0x3820u, 0x5840u, 0xA800u, 0x15000u, 0xA000u, 0x14000u
};
__constant__ int ESRC[38] = {15,13,16,14,11,5,6,5,5,6,7,8,1,0,0,1,2,3,4,
                             13,11,14,12,12,11,12,6,7,8,9,10,2,1,2,3,4,5,6};
__constant__ int EDST[38] = {13,11,14,12,12,11,12,6,7,8,9,10,2,1,2,3,4,5,6,
                             15,13,16,14,11,5,6,5,5,6,7,8,1,0,0,1,2,3,4};

static inline int cdiv(int a, int b) { return (a + b - 1) / b; }

// =======================================================================
// fp16 wmma GEMM (TN): C[M,N] = A[M,K](half,row) * B[N,K](half,row)^T
// HC=false: C fp32.  HC=true: C half (fragment staged through smem).
// =======================================================================
__device__ __forceinline__ uint32_t smem_u32h(const void* p) {
    return (uint32_t)__cvta_generic_to_shared(p);
}
__device__ __forceinline__ void cpasync16h(uint32_t dst, const void* src) {
    asm volatile("cp.async.cg.shared.global [%0], [%1], 16;" :: "r"(dst), "l"(src));
}

template<bool HC>
__global__ void __launch_bounds__(256, 2) hgemm_tn(
    int M, int N, int K,
    const __half* __restrict__ A, int lda,
    const __half* __restrict__ B, int ldb,
    void* __restrict__ Cv, int ldc)
{
    __shared__ __align__(16) __half As[2][128][40];
    __shared__ __align__(16) __half Bs[2][128][40];
    const int tid  = threadIdx.x;
    const int warp = tid >> 5;
    const int wm   = warp & 3;
    const int wn   = warp >> 2;
    const int bm   = blockIdx.y * 128;
    const int bn   = blockIdx.x * 128;
    const int T    = K >> 5;

    wmma::fragment<wmma::accumulator, 16, 16, 16, float> acc[2][4];
#pragma unroll
    for (int i = 0; i < 2; i++)
#pragma unroll
        for (int j = 0; j < 4; j++) wmma::fill_fragment(acc[i][j], 0.0f);

    const uint32_t as_base = smem_u32h(&As[0][0][0]);
    const uint32_t bs_base = smem_u32h(&Bs[0][0][0]);
    const uint32_t stage_bytes = 128 * 40 * 2;

    auto load_stage = [&](int s, int kt) {
        const __half* a = A + (size_t)bm * lda + kt * 32;
        const __half* b = B + (size_t)bn * ldb + kt * 32;
#pragma unroll
        for (int i = 0; i < 2; i++) {
            int q = tid + i * 256;
            int row = q >> 2, c = q & 3;
            cpasync16h(as_base + s * stage_bytes + row * 80 + c * 16,
                       a + (size_t)row * lda + c * 8);
        }
#pragma unroll
        for (int i = 0; i < 2; i++) {
            int q = tid + i * 256;
            int row = q >> 2, c = q & 3;
            cpasync16h(bs_base + s * stage_bytes + row * 80 + c * 16,
                       b + (size_t)row * ldb + c * 8);
        }
    };

    load_stage(0, 0);
    asm volatile("cp.async.commit_group;" ::: "memory");

    for (int kt = 0; kt < T; kt++) {
        const int s = kt & 1;
        if (kt + 1 < T) {
            load_stage(s ^ 1, kt + 1);
            asm volatile("cp.async.commit_group;" ::: "memory");
            asm volatile("cp.async.wait_group 1;" ::: "memory");
        } else {
            asm volatile("cp.async.wait_group 0;" ::: "memory");
        }
        __syncthreads();

#pragma unroll
        for (int kk = 0; kk < 32; kk += 16) {
            wmma::fragment<wmma::matrix_a, 16, 16, 16, __half, wmma::row_major> af[2];
            wmma::load_matrix_sync(af[0], &As[s][wm * 32][kk], 40);
            wmma::load_matrix_sync(af[1], &As[s][wm * 32 + 16][kk], 40);
#pragma unroll
            for (int j = 0; j < 4; j++) {
                wmma::fragment<wmma::matrix_b, 16, 16, 16, __half, wmma::col_major> bf;
                wmma::load_matrix_sync(bf, &Bs[s][wn * 64 + j * 16][kk], 40);
                wmma::mma_sync(acc[0][j], af[0], bf, acc[0][j]);
                wmma::mma_sync(acc[1][j], af[1], bf, acc[1][j]);
            }
        }
        __syncthreads();
    }

    if (!HC) {
        float* C = (float*)Cv;
#pragma unroll
        for (int i = 0; i < 2; i++)
#pragma unroll
            for (int j = 0; j < 4; j++)
                wmma::store_matrix_sync(
                    &C[(size_t)(bm + wm * 32 + i * 16) * ldc + bn + wn * 64 + j * 16],
                    acc[i][j], ldc, wmma::mem_row_major);
    } else {
        __half* Ch = (__half*)Cv;
        float* stg = reinterpret_cast<float*>(&As[0][0][0]) + warp * (16 * 24);
        const int lane = tid & 31;
        const int r  = lane >> 1;
        const int c0 = (lane & 1) * 8;
#pragma unroll
        for (int i = 0; i < 2; i++)
#pragma unroll
            for (int j = 0; j < 4; j++) {
                __syncwarp();
                wmma::store_matrix_sync(stg, acc[i][j], 24, wmma::mem_row_major);
                __syncwarp();
                __half2 h2[4];
#pragma unroll
                for (int q = 0; q < 4; q++)
                    h2[q] = __floats2half2_rn(stg[r * 24 + c0 + 2 * q],
                                              stg[r * 24 + c0 + 2 * q + 1]);
                size_t grow = (size_t)(bm + wm * 32 + i * 16 + r);
                size_t gcol = (size_t)(bn + wn * 64 + j * 16 + c0);
                *reinterpret_cast<uint4*>(&Ch[grow * ldc + gcol]) =
                    *reinterpret_cast<uint4*>(h2);
            }
    }
}

// ---------------- weight conversion kernels ----------------
__global__ void f2h3_kernel(const float* __restrict__ a, __half* __restrict__ oa, size_t na,
                            const float* __restrict__ b, __half* __restrict__ ob, size_t nb,
                            const float* __restrict__ c, __half* __restrict__ oc, size_t nc)
{
    size_t total = na + nb + nc;
    for (size_t i = (size_t)blockIdx.x * blockDim.x + threadIdx.x; i < total;
         i += (size_t)gridDim.x * blockDim.x) {
        if (i < na)            oa[i]           = __float2half(a[i]);
        else if (i < na + nb)  ob[i - na]      = __float2half(b[i - na]);
        else                   oc[i - na - nb] = __float2half(c[i - na - nb]);
    }
}

__global__ void transpose_h_kernel(const float* __restrict__ in, __half* __restrict__ out,
                                   int R, int Ccols)
{
    __shared__ float t[32][33];
    int bx = blockIdx.x * 32, by = blockIdx.y * 32;
#pragma unroll
    for (int dy = 0; dy < 32; dy += 8) {
        int r = by + threadIdx.y + dy, c = bx + threadIdx.x;
        if (r < R && c < Ccols) t[threadIdx.y + dy][threadIdx.x] = in[(size_t)r * Ccols + c];
    }
    __syncthreads();
#pragma unroll
    for (int dy = 0; dy < 32; dy += 8) {
        int r = bx + threadIdx.y + dy, c = by + threadIdx.x;
        if (r < Ccols && c < R) out[(size_t)r * R + c] = __float2half(t[threadIdx.x][threadIdx.y + dy]);
    }
}

// ---------------- fp32 GEMM (classifier) ----------------
template<int BM, int BN, int BK, int TM, int TN, int TB>
__global__ void sgemm_kernel(int M, int N, int K,
                             const float* __restrict__ A, int lda,
                             const float* __restrict__ B, int ldb,
                             float* __restrict__ C, int ldc,
                             const float* __restrict__ bias,
                             const float* __restrict__ addmat, int ldadd)
{
    constexpr int THREADS = (BM/TM) * (BN/TN);
    __shared__ float As[BK][BM];
    __shared__ float Bs[BK][BN];
    const int tid = threadIdx.x;
    const int bm = blockIdx.y * BM;
    const int bn = blockIdx.x * BN;
    const int tx = tid % (BN/TN);
    const int ty = tid / (BN/TN);

    float acc[TM][TN];
#pragma unroll
    for (int i = 0; i < TM; i++)
#pragma unroll
        for (int j = 0; j < TN; j++) acc[i][j] = 0.f;

    for (int k0 = 0; k0 < K; k0 += BK) {
        for (int i = tid; i < BM*BK; i += THREADS) {
            int m = i / BK, k = i % BK;
            int gm = bm + m, gk = k0 + k;
            As[k][m] = (gm < M && gk < K) ? A[(size_t)gm * lda + gk] : 0.f;
        }
        if (TB == 0) {
            for (int i = tid; i < BK*BN; i += THREADS) {
                int k = i / BN, n = i % BN;
                int gk = k0 + k, gn = bn + n;
                Bs[k][n] = (gk < K && gn < N) ? B[(size_t)gk * ldb + gn] : 0.f;
            }
        } else {
            for (int i = tid; i < BK*BN; i += THREADS) {
                int n = i / BK, k = i % BK;
                int gk = k0 + k, gn = bn + n;
                Bs[k][n] = (gk < K && gn < N) ? B[(size_t)gn * ldb + gk] : 0.f;
            }
        }
        __syncthreads();
#pragma unroll
        for (int k = 0; k < BK; k++) {
            float ra[TM], rb[TN];
#pragma unroll
            for (int i = 0; i < TM; i++) ra[i] = As[k][ty*TM + i];
#pragma unroll
            for (int j = 0; j < TN; j++) rb[j] = Bs[k][tx*TN + j];
#pragma unroll
            for (int i = 0; i < TM; i++)
#pragma unroll
                for (int j = 0; j < TN; j++) acc[i][j] += ra[i] * rb[j];
        }
        __syncthreads();
    }

#pragma unroll
    for (int i = 0; i < TM; i++) {
        int gm = bm + ty*TM + i;
        if (gm >= M) continue;
#pragma unroll
        for (int j = 0; j < TN; j++) {
            int gn = bn + tx*TN + j;
            if (gn >= N) continue;
            float v = acc[i][j];
            if (bias)   v += bias[gn];
            if (addmat) v += addmat[(size_t)gm * ldadd + gn];
            C[(size_t)gm * ldc + gn] = v;
        }
    }
}

// ---------------- GAT layer 1: fused (pose @ W1) + attention -> half xh ----------------
__global__ void gat_attn1_fused(const float* __restrict__ pose1,
                                const float* __restrict__ pose2,
                                const float* __restrict__ W1,
                                const float* __restrict__ a_src,
                                const float* __restrict__ a_dst,
                                const float* __restrict__ bias,
                                __half* __restrict__ out)
{
    __shared__ float ps[17*3];
    __shared__ float w1s[3*64];
    __shared__ float hb[17*64];
    __shared__ float ss[17], sd[17];
    __shared__ float alpha[17*17];
    const int g = blockIdx.x >> 3;
    const int head = blockIdx.x & 7;
    const int tid = threadIdx.x;
    int p = g / GPOSE, r = g % GPOSE;
    const float* pose = (p == 0 ? pose1 : pose2) + (size_t)r * 51;

    if (tid < 51) ps[tid] = pose[tid];
    if (tid >= 64 && tid < 128) {
        int d = tid - 64;
#pragma unroll
        for (int k = 0; k < 3; k++) w1s[k*64 + d] = W1[k*512 + head*64 + d];
    }
    __syncthreads();
    for (int idx = tid; idx < 17*64; idx += 128) {
        int n = idx >> 6, d = idx & 63;
        hb[idx] = ps[n*3]*w1s[d] + ps[n*3+1]*w1s[64+d] + ps[n*3+2]*w1s[128+d];
    }
    __syncthreads();
    if (tid < 34) {
        int n = tid % 17;
        const float* a = (tid < 17 ? a_src : a_dst) + head*64;
        float s = 0.f;
        for (int d = 0; d < 64; d++) s += hb[n*64 + d] * a[d];
        if (tid < 17) ss[n] = s; else sd[n] = s;
    }
    __syncthreads();
    if (tid < 17) {
        int i = tid;
        unsigned m = ADJMASK[i];
        float ev[17];
        float mx = -1e30f;
#pragma unroll
        for (int j = 0; j < 17; j++) {
            if ((m >> j) & 1u) {
                float e = sd[i] + ss[j];
                e = e > 0.f ? e : 0.2f * e;
                ev[j] = e;
                if (e > mx) mx = e;
            }
        }
        float sum = 0.f;
#pragma unroll
        for (int j = 0; j < 17; j++) {
            float a_ = 0.f;
            if ((m >> j) & 1u) { a_ = expf(ev[j] - mx); sum += a_; }
            alpha[i*17 + j] = a_;
        }
        float inv = 1.f / sum;
#pragma unroll
        for (int j = 0; j < 17; j++) alpha[i*17 + j] *= inv;
    }
    __syncthreads();
    for (int idx = tid; idx < 17*64; idx += 128) {
        int i = idx >> 6, d = idx & 63;
        float accv = 0.f;
#pragma unroll
        for (int j = 0; j < 17; j++) accv += alpha[i*17 + j] * hb[j*64 + d];
        float v = accv + bias[head*64 + d];
        v = v > 0.f ? v : expm1f(v);
        out[(size_t)(g*17 + i) * 512 + head*64 + d] = __float2half(v);
    }
}

// ---------------- GAT layer 2 attention, half2 aggregation -> half xh ----------------
__global__ void gat_attn2_h2(const __half* __restrict__ h,
                             const float* __restrict__ a_src,
                             const float* __restrict__ a_dst,
                             const float* __restrict__ bias,
                             __half* __restrict__ out)
{
    __shared__ __half2 hb2[17*64];        // D=128 as 64 half2
    __shared__ float ss[17], sd[17];
    __shared__ float alpha[17*17];
    const int g = blockIdx.x >> 3;
    const int head = blockIdx.x & 7;
    const int tid = threadIdx.x;

    for (int idx = tid; idx < 17*64; idx += 128) {
        int n = idx >> 6, d2 = idx & 63;
        hb2[idx] = *reinterpret_cast<const __half2*>(
            &h[(size_t)(g*17 + n) * 1024 + head*128 + 2*d2]);
    }
    __syncthreads();
    if (tid < 34) {
        int n = tid % 17;
        const float* a = (tid < 17 ? a_src : a_dst) + head*128;
        float s = 0.f;
        for (int d2 = 0; d2 < 64; d2++) {
            float2 f = __half22float2(hb2[n*64 + d2]);
            s += f.x * a[2*d2] + f.y * a[2*d2 + 1];
        }
        if (tid < 17) ss[n] = s; else sd[n] = s;
    }
    __syncthreads();
    if (tid < 17) {
        int i = tid;
        unsigned m = ADJMASK[i];
        float ev[17];
        float mx = -1e30f;
#pragma unroll
        for (int j = 0; j < 17; j++) {
            if ((m >> j) & 1u) {
                float e = sd[i] + ss[j];
                e = e > 0.f ? e : 0.2f * e;
                ev[j] = e;
                if (e > mx) mx = e;
            }
        }
        float sum = 0.f;
#pragma unroll
        for (int j = 0; j < 17; j++) {
            float a_ = 0.f;
            if ((m >> j) & 1u) { a_ = expf(ev[j] - mx); sum += a_; }
            alpha[i*17 + j] = a_;
        }
        float inv = 1.f / sum;
#pragma unroll
        for (int j = 0; j < 17; j++) alpha[i*17 + j] *= inv;
    }
    __syncthreads();
    for (int idx = tid; idx < 17*64; idx += 128) {
        int i = idx >> 6, d2 = idx & 63;
        float ax = 0.f, ay = 0.f;
#pragma unroll
        for (int j = 0; j < 17; j++) {
            float a_ = alpha[i*17 + j];
            float2 f = __half22float2(hb2[j*64 + d2]);
            ax += a_ * f.x;
            ay += a_ * f.y;
        }
        ax += bias[head*128 + 2*d2];
        ay += bias[head*128 + 2*d2 + 1];
        ax = ax > 0.f ? ax : expm1f(ax);
        ay = ay > 0.f ? ay : expm1f(ay);
        *reinterpret_cast<__half2*>(
            &out[(size_t)(g*17 + i) * 1024 + head*128 + 2*d2]) =
            __floats2half2_rn(ax, ay);
    }
}

// ---------------- GAT layer 3 (mean heads, half2) + BN fold -> half comb ----------------
__global__ void gat_attn_mean_h2(const __half* __restrict__ h,
                                 const float* __restrict__ a_src,
                                 const float* __restrict__ a_dst,
                                 const float* __restrict__ b3,
                                 __half* __restrict__ comb,
                                 const float* __restrict__ bn_g,
                                 const float* __restrict__ bn_b,
                                 const float* __restrict__ bn_mean,
                                 const float* __restrict__ bn_var)
{
    __shared__ __half2 hb2[17*128];       // D=256 as 128 half2
    __shared__ float2 accs[17*128];
    __shared__ float ss[17], sd[17];
    __shared__ float alpha[17*17];
    const int g = blockIdx.x;
    const int tid = threadIdx.x;

    for (int idx = tid; idx < 17*128; idx += blockDim.x) accs[idx] = make_float2(0.f, 0.f);

    for (int head = 0; head < 8; head++) {
        __syncthreads();
        for (int idx = tid; idx < 17*128; idx += blockDim.x) {
            int n = idx >> 7, d2 = idx & 127;
            hb2[idx] = *reinterpret_cast<const __half2*>(
                &h[(size_t)(g*17 + n) * 2048 + head*256 + 2*d2]);
        }
        __syncthreads();
        if (tid < 34) {
            int n = tid % 17;
            const float* a = (tid < 17 ? a_src : a_dst) + head*256;
            float s = 0.f;
            for (int d2 = 0; d2 < 128; d2++) {
                float2 f = __half22float2(hb2[n*128 + d2]);
                s += f.x * a[2*d2] + f.y * a[2*d2 + 1];
            }
            if (tid < 17) ss[n] = s; else sd[n] = s;
        }
        __syncthreads();
        if (tid < 17) {
            int i = tid;
            unsigned m = ADJMASK[i];
            float ev[17];
            float mx = -1e30f;
#pragma unroll
            for (int j = 0; j < 17; j++) {
                if ((m >> j) & 1u) {
                    float e = sd[i] + ss[j];
                    e = e > 0.f ? e : 0.2f * e;
                    ev[j] = e;
                    if (e > mx) mx = e;
                }
            }
            float sum = 0.f;
#pragma unroll
            for (int j = 0; j < 17; j++) {
                float a_ = 0.f;
                if ((m >> j) & 1u) { a_ = expf(ev[j] - mx); sum += a_; }
                alpha[i*17 + j] = a_;
            }
            float inv = 1.f / sum;
#pragma unroll
            for (int j = 0; j < 17; j++) alpha[i*17 + j] *= inv;
        }
        __syncthreads();
        for (int idx = tid; idx < 17*128; idx += blockDim.x) {
            int i = idx >> 7, d2 = idx & 127;
            float ax = 0.f, ay = 0.f;
#pragma unroll
            for (int j = 0; j < 17; j++) {
                float a_ = alpha[i*17 + j];
                float2 f = __half22float2(hb2[j*128 + d2]);
                ax += a_ * f.x;
                ay += a_ * f.y;
            }
            accs[idx].x += ax;
            accs[idx].y += ay;
        }
    }
    __syncthreads();
    int p = g / GPOSE, r = g % GPOSE, b = r / TT, t = r % TT;
    float scale = bn_g[t] * rsqrtf(bn_var[t] + 1e-5f);
    float mu = bn_mean[t], beta = bn_b[t];
    size_t base = ((size_t)(p*BB + b) * TT + t) * FEAT;
    for (int idx = tid; idx < 17*128; idx += blockDim.x) {
        int n = idx >> 7, d2 = idx & 127;
        float vx = accs[idx].x * 0.125f + b3[2*d2];
        float vy = accs[idx].y * 0.125f + b3[2*d2 + 1];
        vx = (vx - mu) * scale + beta;
        vy = (vy - mu) * scale + beta;
        *reinterpret_cast<__half2*>(&comb[base + n*256 + 2*d2]) =
            __floats2half2_rn(vx, vy);
    }
}

// ---------------- Edge features + FC + BN fold -> half comb ----------------
__global__ void edge_fc_kernel(const float* __restrict__ pose1,
                               const float* __restrict__ pose2,
                               const float* __restrict__ fc_w,
                               const float* __restrict__ fc_b,
                               __half* __restrict__ comb,
                               const float* __restrict__ bn_g,
                               const float* __restrict__ bn_b,
                               const float* __restrict__ bn_mean,
                               const float* __restrict__ bn_var)
{
    __shared__ float feat[76];
    const int g = blockIdx.x;
    const int tid = threadIdx.x;
    int p = g / GPOSE, r = g % GPOSE, b = r / TT, t = r % TT;
    const float* pose = (p == 0 ? pose1 : pose2) + (size_t)r * 17 * 3;
    if (tid < 38) {
        int s = ESRC[tid], d = EDST[tid];
        float vx = pose[d*3 + 0] - pose[s*3 + 0];
        float vy = pose[d*3 + 1] - pose[s*3 + 1];
        feat[2*tid]     = sqrtf(vx*vx + vy*vy);
        feat[2*tid + 1] = atan2f(vy, vx);
    }
    __syncthreads();
    float scale = bn_g[t] * rsqrtf(bn_var[t] + 1e-5f);
    float mu = bn_mean[t], beta = bn_b[t];
    size_t base = ((size_t)(p*BB + b) * TT + t) * FEAT + 17*256;
    if (tid < 128) {
        float s0 = fc_b[tid], s1 = fc_b[tid];
        for (int j = 0; j < 38; j++) {
            float w = fc_w[j*128 + tid];
            s0 += feat[j] * w;
            s1 += feat[38 + j] * w;
        }
        comb[base + tid]       = __float2half((s0 - mu) * scale + beta);
        comb[base + 128 + tid] = __float2half((s1 - mu) * scale + beta);
    }
}

// ---------------- Misc small kernels ----------------
__global__ void bias_sum_kernel(const float* bihf, const float* bhhf,
                                const float* bihb, const float* bhhb)
{
    int i = blockIdx.x * blockDim.x + threadIdx.x;
    if (i < 2048) {
        S_biasf[i] = bihf[i] + bhhf[i];
        S_biasb[i] = bihb[i] + bhhb[i];
    }
}
__global__ void zero_state_kernel()
{
    int i = blockIdx.x * blockDim.x + threadIdx.x;
    if (i < 2*BB*LSTM_H) { S_cst[i] = 0.f; S_hh[i] = __float2half(0.f); }
}
__device__ __forceinline__ float sigf(float x) { return 1.f / (1.f + expf(-x)); }

__global__ void lstm_cell2(const float* __restrict__ hh,
                           const float* __restrict__ xp, int xstride,
                           const float* __restrict__ bias,
                           float* __restrict__ c, __half* __restrict__ hhalf,
                           float* __restrict__ out_last, int write_last)
{
    int idx = blockIdx.x * blockDim.x + threadIdx.x;
    if (idx >= 2*BB*LSTM_H) return;
    int m = idx / LSTM_H, j = idx % LSTM_H;
    const float* x = xp + (size_t)m * xstride;
    float gi = x[j]        + bias[j];
    float gf = x[512 + j]  + bias[512 + j];
    float gg = x[1024 + j] + bias[1024 + j];
    float go = x[1536 + j] + bias[1536 + j];
    if (hh) {
        const float* hm = hh + (size_t)m * 2048;
        gi += hm[j]; gf += hm[512 + j]; gg += hm[1024 + j]; go += hm[1536 + j];
    }
    float cn = sigf(gf) * c[idx] + sigf(gi) * tanhf(gg);
    float hn = sigf(go) * tanhf(cn);
    c[idx] = cn;
    hhalf[idx] = __float2half(hn);
    if (write_last) out_last[(size_t)m * (2*LSTM_H) + j] = hn;
}

__global__ void lstm_bcell_kernel(const float* __restrict__ gates,
                                  const float* __restrict__ bias,
                                  float* __restrict__ out)
{
    int idx = blockIdx.x * blockDim.x + threadIdx.x;
    if (idx >= 2*BB*LSTM_H) return;
    int m = idx / LSTM_H, j = idx % LSTM_H;
    const float* gm = gates + (size_t)m * 2048;
    float gi = gm[j]        + bias[j];
    float gg = gm[1024 + j] + bias[1024 + j];
    float go = gm[1536 + j] + bias[1536 + j];
    float cn = sigf(gi) * tanhf(gg);
    out[(size_t)m * (2*LSTM_H) + LSTM_H + j] = sigf(go) * tanhf(cn);
}

// ---------------- Host driver ----------------
extern "C" void kernel_launch(void* const* d_in, const int* in_sizes, int n_in,
                              void* d_out, int out_size)
{
    const float* pose1 = (const float*)d_in[0];
    const float* pose2 = (const float*)d_in[1];
    const float* W1  = (const float*)d_in[3];
    const float* as1 = (const float*)d_in[4];
    const float* ad1 = (const float*)d_in[5];
    const float* b1  = (const float*)d_in[6];
    const float* W2  = (const float*)d_in[7];
    const float* as2 = (const float*)d_in[8];
    const float* ad2 = (const float*)d_in[9];
    const float* b2  = (const float*)d_in[10];
    const float* W3  = (const float*)d_in[11];
    const float* as3 = (const float*)d_in[12];
    const float* ad3 = (const float*)d_in[13];
    const float* b3  = (const float*)d_in[14];
    const float* fc_w = (const float*)d_in[15];
    const float* fc_b = (const float*)d_in[16];
    const float* bn_g = (const float*)d_in[17];
    const float* bn_b = (const float*)d_in[18];
    const float* bn_mean = (const float*)d_in[19];
    const float* bn_var  = (const float*)d_in[20];
    const float* Wih_f = (const float*)d_in[21];
    const float* Whh_f = (const float*)d_in[22];
    const float* bih_f = (const float*)d_in[23];
    const float* bhh_f = (const float*)d_in[24];
    const float* Wih_b = (const float*)d_in[25];
    const float* Whh_b = (const float*)d_in[26];
    const float* bih_b = (const float*)d_in[27];
    const float* bhh_b = (const float*)d_in[28];
    const float* cls_w = (const float*)d_in[29];
    const float* cls_b = (const float*)d_in[30];

    float* out = (float*)d_out;

    float  *g_xproj, *g_gates, *g_gatesb, *g_cst, *g_biasf, *g_biasb;
    __half *g_hbig, *g_xh, *g_combh, *g_hh, *g_w2t, *g_w3t, *g_wihf, *g_wihb, *g_whhh;
    cudaGetSymbolAddress((void**)&g_hbig, S_hbig);
    cudaGetSymbolAddress((void**)&g_xh, S_xh);
    cudaGetSymbolAddress((void**)&g_combh, S_combh);
    cudaGetSymbolAddress((void**)&g_xproj, S_xproj);
    cudaGetSymbolAddress((void**)&g_gates, S_gates);
    cudaGetSymbolAddress((void**)&g_gatesb, S_gatesb);
    cudaGetSymbolAddress((void**)&g_hh, S_hh);
    cudaGetSymbolAddress((void**)&g_cst, S_cst);
    cudaGetSymbolAddress((void**)&g_biasf, S_biasf);
    cudaGetSymbolAddress((void**)&g_biasb, S_biasb);
    cudaGetSymbolAddress((void**)&g_w2t, S_w2t);
    cudaGetSymbolAddress((void**)&g_w3t, S_w3t);
    cudaGetSymbolAddress((void**)&g_wihf, S_wihf);
    cudaGetSymbolAddress((void**)&g_wihb, S_wihb);
    cudaGetSymbolAddress((void**)&g_whhh, S_whhh);

    // 1: W2^T
    transpose_h_kernel<<<dim3(1024/32, 512/32), dim3(32, 8)>>>(W2, g_w2t, 512, 1024);
    // 2: GAT layer 1 fused (pose@W1 + attention) -> xh
    gat_attn1_fused<<<GTOT*HEADS, 128>>>(pose1, pose2, W1, as1, ad1, b1, g_xh);
    // 3: GAT layer 2 GEMM (104448 x 1024 x 512), half C
    hgemm_tn<true><<<dim3(1024/128, ROWS_TOT/128), 256>>>(
        ROWS_TOT, 1024, 512, g_xh, 512, g_w2t, 512, g_hbig, 1024);
    // 4: GAT layer 2 attention (half2)
    gat_attn2_h2<<<GTOT*HEADS, 128>>>(g_hbig, as2, ad2, b2, g_xh);
    // 5: W3^T
    transpose_h_kernel<<<dim3(2048/32, 1024/32), dim3(32, 8)>>>(W3, g_w3t, 1024, 2048);
    // 6: GAT layer 3 GEMM (104448 x 2048 x 1024), half C
    hgemm_tn<true><<<dim3(2048/128, ROWS_TOT/128), 256>>>(
        ROWS_TOT, 2048, 1024, g_xh, 1024, g_w3t, 1024, g_hbig, 2048);
    // 7: GAT layer 3 attention (mean heads, half2) + BN -> comb
    gat_attn_mean_h2<<<GTOT, 256>>>(g_hbig, as3, ad3, b3, g_combh,
                                    bn_g, bn_b, bn_mean, bn_var);
    // 8: edge features + FC + BN -> comb
    edge_fc_kernel<<<GTOT, 128>>>(pose1, pose2, fc_w, fc_b, g_combh,
                                  bn_g, bn_b, bn_mean, bn_var);
    // 9: convert Wih_f, Wih_b, Whh_f to half (single launch)
    f2h3_kernel<<<2048, 256>>>(Wih_f, g_wihf, (size_t)2048 * FEAT,
                               Wih_b, g_wihb, (size_t)2048 * FEAT,
                               Whh_f, g_whhh, (size_t)2048 * LSTM_H);
    // 10: gate biases
    bias_sum_kernel<<<8, 256>>>(bih_f, bhh_f, bih_b, bhh_b);
    // 11: forward input projection (6144 x 2048 x 4608), fp32 C
    hgemm_tn<false><<<dim3(2048/128, (2*BB*TT)/128), 256>>>(
        2*BB*TT, 2048, FEAT, g_combh, FEAT, g_wihf, FEAT, g_xproj, 2048);
    // 12: backward single step at t=23 (256 x 2048 x 4608)
    hgemm_tn<false><<<dim3(2048/128, 2), 256>>>(
        2*BB, 2048, FEAT, g_combh + (size_t)23*FEAT, TT*FEAT, g_wihb, FEAT,
        g_gatesb, 2048);
    lstm_bcell_kernel<<<cdiv(2*BB*LSTM_H, 256), 256>>>(g_gatesb, g_biasb, out);

    // forward recurrence
    zero_state_kernel<<<cdiv(2*BB*LSTM_H, 256), 256>>>();
    lstm_cell2<<<cdiv(2*BB*LSTM_H, 256), 256>>>(
        nullptr, g_xproj, TT*2048, g_biasf, g_cst, g_hh, out, 0);
    for (int t = 1; t < TT; t++) {
        hgemm_tn<false><<<dim3(2048/128, 2), 256>>>(
            2*BB, 2048, LSTM_H, g_hh, LSTM_H, g_whhh, LSTM_H, g_gates, 2048);
        lstm_cell2<<<cdiv(2*BB*LSTM_H, 256), 256>>>(
            g_gates, g_xproj + (size_t)t*2048, TT*2048, g_biasf, g_cst, g_hh,
            out, (t == TT-1) ? 1 : 0);
    }

    // classifier (fp32)
    {
        dim3 grid(cdiv(NCLS, 64), cdiv(2*BB, 64));
        sgemm_kernel<64,64,8,4,4,0><<<grid, 256>>>(
            2*BB, NCLS, 2*LSTM_H, out, 2*LSTM_H, cls_w, NCLS,
            out + OUT_LSTM, NCLS, cls_b, nullptr, 0);
    }
}